// round 1
// baseline (speedup 1.0000x reference)
#include <cuda_runtime.h>
#include <math.h>

// ---------------- scratch (static device globals; no allocation) ----------------
__device__ float g_src_tran [16*512*2048];   // relu(src@W_src+b)  -> K|V halves
__device__ float g_tgt_query[16*512*1024];   // relu(tgt@W_tgt+b)  -> Q
__device__ float g_tgt_update[16*512*1024];  // attention output

// ---------------- SGEMM: C = relu(A @ B + bias) ----------------
// A is a "virtual concat": first kA0 columns come from A0 (ld lda0),
// the rest from A1 (ld lda1). B is [K,N] row-major. All dims multiples
// of the tile sizes for this problem, so no bounds checks.
#define BM 128
#define BN 128
#define BK 8

__global__ void __launch_bounds__(256)
sgemm_relu(const float* __restrict__ A0, int lda0, int kA0,
           const float* __restrict__ A1, int lda1,
           const float* __restrict__ B, int ldb,
           const float* __restrict__ bias,
           float* __restrict__ C, int ldc, int K)
{
    __shared__ float As[BK][BM];
    __shared__ float Bs[BK][BN];

    const int tid = threadIdx.x;
    const int tx = tid & 15, ty = tid >> 4;
    const int rowBase = blockIdx.y * BM;
    const int colBase = blockIdx.x * BN;

    const int aRow = tid >> 1, aCol = (tid & 1) * 4;
    const int bRow = tid >> 5, bCol = (tid & 31) * 4;

    float acc[8][8] = {};

    const int ktiles = K / BK;
    for (int kt = 0; kt < ktiles; ++kt) {
        const int k0 = kt * BK;
        const float* Ap; int lda, kk;
        if (k0 < kA0) { Ap = A0; lda = lda0; kk = k0; }
        else          { Ap = A1; lda = lda1; kk = k0 - kA0; }

        float4 av = *(const float4*)(Ap + (size_t)(rowBase + aRow) * lda + kk + aCol);
        float4 bv = *(const float4*)(B  + (size_t)(k0 + bRow) * ldb + colBase + bCol);

        __syncthreads();  // previous tile's compute done
        As[aCol + 0][aRow] = av.x;
        As[aCol + 1][aRow] = av.y;
        As[aCol + 2][aRow] = av.z;
        As[aCol + 3][aRow] = av.w;
        *(float4*)&Bs[bRow][bCol] = bv;
        __syncthreads();

        #pragma unroll
        for (int k = 0; k < BK; ++k) {
            float a[8], b[8];
            *(float4*)(a)     = *(const float4*)&As[k][ty * 8];
            *(float4*)(a + 4) = *(const float4*)&As[k][ty * 8 + 4];
            *(float4*)(b)     = *(const float4*)&Bs[k][tx * 8];
            *(float4*)(b + 4) = *(const float4*)&Bs[k][tx * 8 + 4];
            #pragma unroll
            for (int i = 0; i < 8; ++i)
                #pragma unroll
                for (int j = 0; j < 8; ++j)
                    acc[i][j] += a[i] * b[j];
        }
    }

    #pragma unroll
    for (int i = 0; i < 8; ++i) {
        const int row = rowBase + ty * 8 + i;
        float* Crow = C + (size_t)row * ldc + colBase + tx * 8;
        #pragma unroll
        for (int j = 0; j < 8; ++j) {
            float v = acc[i][j] + bias[colBase + tx * 8 + j];
            Crow[j] = v > 0.f ? v : 0.f;
        }
    }
}

// ---------------- attention ----------------
// One block = one (b, h) and one 32-row q tile. Full 512-col score row in smem.
// smem: qs[32][132] + ts[64][132] + ss[32][512]  = 116224 B (dynamic)
#define LDP 132
#define ATTN_SMEM ((32*LDP + 64*LDP + 32*512) * 4)

__global__ void __launch_bounds__(256)
attn_kernel(const float* __restrict__ Q, const float* __restrict__ KV,
            float* __restrict__ O)
{
    extern __shared__ float sm[];
    float* qs = sm;                       // [32][LDP]
    float* ts = sm + 32 * LDP;            // [64][LDP]   (K tile, then V tile)
    float* ss = sm + 32 * LDP + 64 * LDP; // [32][512]

    const int tid = threadIdx.x;
    const int bh = blockIdx.y;
    const int b = bh >> 3, h = bh & 7;
    const int rt = blockIdx.x;            // q-row tile (32 rows), 0..15
    const float scale = 0.08838834764831845f;  // 1/sqrt(128)

    const float* qg = Q  + ((size_t)(b * 512 + rt * 32)) * 1024 + h * 128;
    const float* kg = KV + ((size_t)(b * 512)) * 2048 + h * 128;
    const float* vg = kg + 1024;
    float*       og = O  + ((size_t)(b * 512 + rt * 32)) * 1024 + h * 128;

    // load Q tile (pre-scaled)
    for (int s = tid; s < 1024; s += 256) {
        int r = s >> 5, c = (s & 31) * 4;
        float4 v = *(const float4*)(qg + (size_t)r * 1024 + c);
        qs[r * LDP + c + 0] = v.x * scale;
        qs[r * LDP + c + 1] = v.y * scale;
        qs[r * LDP + c + 2] = v.z * scale;
        qs[r * LDP + c + 3] = v.w * scale;
    }

    const int r  = tid >> 3;   // q row this thread owns (0..31)
    const int c8 = tid & 7;

    // ---- scores: Q @ K^T ----
    for (int st = 0; st < 8; ++st) {
        __syncthreads();
        for (int s = tid; s < 2048; s += 256) {
            int kr = s >> 5, kc = (s & 31) * 4;
            *(float4*)&ts[kr * LDP + kc] =
                *(const float4*)(kg + (size_t)(st * 64 + kr) * 2048 + kc);
        }
        __syncthreads();

        float acc[8] = {};
        #pragma unroll 4
        for (int d = 0; d < 128; ++d) {
            float qv = qs[r * LDP + d];
            #pragma unroll
            for (int j = 0; j < 8; ++j)
                acc[j] += qv * ts[(c8 + 8 * j) * LDP + d];
        }
        #pragma unroll
        for (int j = 0; j < 8; ++j)
            ss[r * 512 + st * 64 + c8 + 8 * j] = acc[j];
    }
    __syncthreads();

    // ---- softmax (each warp owns 4 rows) ----
    const int warp = tid >> 5, lane = tid & 31;
    for (int rr = 0; rr < 4; ++rr) {
        const int row = warp * 4 + rr;
        float m = -1e30f;
        for (int c = lane; c < 512; c += 32) m = fmaxf(m, ss[row * 512 + c]);
        #pragma unroll
        for (int o = 16; o; o >>= 1) m = fmaxf(m, __shfl_xor_sync(0xffffffffu, m, o));
        float sum = 0.f;
        for (int c = lane; c < 512; c += 32) {
            float e = __expf(ss[row * 512 + c] - m);
            ss[row * 512 + c] = e;
            sum += e;
        }
        #pragma unroll
        for (int o = 16; o; o >>= 1) sum += __shfl_xor_sync(0xffffffffu, sum, o);
        float inv = 1.f / sum;
        for (int c = lane; c < 512; c += 32) ss[row * 512 + c] *= inv;
    }

    // ---- P @ V ----
    float oacc[16] = {};
    const int d8 = tid & 7;   // thread owns dims d8, d8+8, ..., d8+120
    for (int st = 0; st < 8; ++st) {
        __syncthreads();
        for (int s = tid; s < 2048; s += 256) {
            int vr = s >> 5, vc = (s & 31) * 4;
            *(float4*)&ts[vr * LDP + vc] =
                *(const float4*)(vg + (size_t)(st * 64 + vr) * 2048 + vc);
        }
        __syncthreads();

        #pragma unroll 4
        for (int n = 0; n < 64; ++n) {
            float p = ss[r * 512 + st * 64 + n];
            #pragma unroll
            for (int j = 0; j < 16; ++j)
                oacc[j] += p * ts[n * LDP + d8 + 8 * j];
        }
    }
    #pragma unroll
    for (int j = 0; j < 16; ++j)
        og[(size_t)r * 1024 + d8 + 8 * j] = oacc[j];
}

// ---------------- launch ----------------
extern "C" void kernel_launch(void* const* d_in, const int* in_sizes, int n_in,
                              void* d_out, int out_size)
{
    const float* src   = (const float*)d_in[0];
    const float* tgt   = (const float*)d_in[1];
    const float* W_src = (const float*)d_in[2];
    const float* b_src = (const float*)d_in[3];
    const float* W_tgt = (const float*)d_in[4];
    const float* b_tgt = (const float*)d_in[5];
    const float* W_out = (const float*)d_in[6];
    const float* b_out = (const float*)d_in[7];
    float* out = (float*)d_out;

    float *src_tran, *tgt_query, *tgt_update;
    cudaGetSymbolAddress((void**)&src_tran,  g_src_tran);
    cudaGetSymbolAddress((void**)&tgt_query, g_tgt_query);
    cudaGetSymbolAddress((void**)&tgt_update, g_tgt_update);

    cudaFuncSetAttribute(attn_kernel,
                         cudaFuncAttributeMaxDynamicSharedMemorySize, ATTN_SMEM);

    dim3 blk(256);

    // GEMM1: src_tran = relu(src @ W_src + b_src)   [8192,512]x[512,2048]
    sgemm_relu<<<dim3(2048 / BN, 8192 / BM), blk>>>(
        src, 512, 512, nullptr, 0, W_src, 2048, b_src, src_tran, 2048, 512);

    // GEMM2: tgt_query = relu(tgt @ W_tgt + b_tgt)  [8192,512]x[512,1024]
    sgemm_relu<<<dim3(1024 / BN, 8192 / BM), blk>>>(
        tgt, 512, 512, nullptr, 0, W_tgt, 1024, b_tgt, tgt_query, 1024, 512);

    // attention: tgt_update
    attn_kernel<<<dim3(16, 128), blk, ATTN_SMEM>>>(tgt_query, src_tran, tgt_update);

    // GEMM3: out = relu([tgt | tgt_update] @ W_out + b_out)  [8192,1536]x[1536,1024]
    sgemm_relu<<<dim3(1024 / BN, 8192 / BM), blk>>>(
        tgt, 512, 512, tgt_update, 1024, W_out, 1024, b_out, out, 1024, 1536);
}

// round 2
// speedup vs baseline: 4.5326x; 4.5326x over previous
#include <cuda_runtime.h>
#include <math.h>

// ---------------- scratch (static device globals; no allocation) ----------------
__device__ float g_src_tran [16*512*2048];   // relu(src@W_src+b)  -> K|V halves
__device__ float g_tgt_query[16*512*1024];   // relu(tgt@W_tgt+b)  -> Q
__device__ float g_tgt_update[16*512*1024];  // attention output

// ---------------- helpers ----------------
__device__ __forceinline__ unsigned f2tf(float f) {
    unsigned u;
    asm("cvt.rna.tf32.f32 %0, %1;" : "=r"(u) : "f"(f));
    return u;
}
__device__ __forceinline__ float f2tf_f(float f) { return __uint_as_float(f2tf(f)); }

__device__ __forceinline__ void mma_tf32(float (&d)[4], const unsigned (&a)[4],
                                         const unsigned (&b)[2]) {
    asm volatile(
        "mma.sync.aligned.m16n8k8.row.col.f32.tf32.tf32.f32 "
        "{%0,%1,%2,%3}, {%4,%5,%6,%7}, {%8,%9}, {%0,%1,%2,%3};\n"
        : "+f"(d[0]), "+f"(d[1]), "+f"(d[2]), "+f"(d[3])
        : "r"(a[0]), "r"(a[1]), "r"(a[2]), "r"(a[3]), "r"(b[0]), "r"(b[1]));
}

// ================= TF32 GEMM: C = relu(A @ B + bias) =================
// A virtual concat: first kA0 cols from A0 (ld lda0), rest from A1 (ld lda1).
// B [K,N] row-major. All dims multiples of tiles.
#define BM 128
#define BN 128
#define BK 16
#define AS_LD 20    // As[row][k], stride%32==4 -> conflict-free A frags
#define BS_LD 136   // Bs[k][n],  stride%32==8 -> conflict-free B frags

__global__ void __launch_bounds__(256)
gemm_tf32_relu(const float* __restrict__ A0, int lda0, int kA0,
               const float* __restrict__ A1, int lda1,
               const float* __restrict__ B, int ldb,
               const float* __restrict__ bias,
               float* __restrict__ C, int ldc, int K)
{
    __shared__ float As[BM * AS_LD];
    __shared__ float Bs[BK * BS_LD];

    const int tid  = threadIdx.x;
    const int lane = tid & 31;
    const int warp = tid >> 5;
    const int wm   = warp & 3;    // 4 warps along M, 32 rows each
    const int wn   = warp >> 2;   // 2 warps along N, 64 cols each
    const int rowBase = blockIdx.y * BM;
    const int colBase = blockIdx.x * BN;

    // staging thread mapping
    const int ar = tid >> 2, ac = (tid & 3) * 4;    // A: rows ar, ar+64; cols ac..ac+3
    const int br = tid >> 5, bc = (tid & 31) * 4;   // B: rows br, br+8;  cols bc..bc+3

    float4 rA0, rA1, rB0, rB1;

    auto load_tile = [&](int kt) {
        const int k0 = kt * BK;
        const float* Ap; int lda, kk;
        if (k0 < kA0) { Ap = A0; lda = lda0; kk = k0; }
        else          { Ap = A1; lda = lda1; kk = k0 - kA0; }
        rA0 = *(const float4*)(Ap + (size_t)(rowBase + ar)      * lda + kk + ac);
        rA1 = *(const float4*)(Ap + (size_t)(rowBase + ar + 64) * lda + kk + ac);
        rB0 = *(const float4*)(B  + (size_t)(k0 + br)     * ldb + colBase + bc);
        rB1 = *(const float4*)(B  + (size_t)(k0 + br + 8) * ldb + colBase + bc);
    };
    auto cvt4 = [](float4 v) {
        float4 o;
        o.x = f2tf_f(v.x); o.y = f2tf_f(v.y); o.z = f2tf_f(v.z); o.w = f2tf_f(v.w);
        return o;
    };

    float acc[2][8][4] = {};

    const int ktiles = K / BK;
    load_tile(0);
    for (int t = 0; t < ktiles; ++t) {
        __syncthreads();
        *(float4*)&As[ar * AS_LD + ac]        = cvt4(rA0);
        *(float4*)&As[(ar + 64) * AS_LD + ac] = cvt4(rA1);
        *(float4*)&Bs[br * BS_LD + bc]        = cvt4(rB0);
        *(float4*)&Bs[(br + 8) * BS_LD + bc]  = cvt4(rB1);
        __syncthreads();
        if (t + 1 < ktiles) load_tile(t + 1);

        #pragma unroll
        for (int kb = 0; kb < BK; kb += 8) {
            unsigned af[2][4], bf[8][2];
            const int m0 = wm * 32 + (lane >> 2);
            const int kk = kb + (lane & 3);
            #pragma unroll
            for (int mf = 0; mf < 2; ++mf) {
                af[mf][0] = __float_as_uint(As[(m0 + mf * 16)     * AS_LD + kk]);
                af[mf][1] = __float_as_uint(As[(m0 + mf * 16 + 8) * AS_LD + kk]);
                af[mf][2] = __float_as_uint(As[(m0 + mf * 16)     * AS_LD + kk + 4]);
                af[mf][3] = __float_as_uint(As[(m0 + mf * 16 + 8) * AS_LD + kk + 4]);
            }
            const int n0 = wn * 64 + (lane >> 2);
            #pragma unroll
            for (int nf = 0; nf < 8; ++nf) {
                bf[nf][0] = __float_as_uint(Bs[kk       * BS_LD + n0 + nf * 8]);
                bf[nf][1] = __float_as_uint(Bs[(kk + 4) * BS_LD + n0 + nf * 8]);
            }
            #pragma unroll
            for (int mf = 0; mf < 2; ++mf)
                #pragma unroll
                for (int nf = 0; nf < 8; ++nf)
                    mma_tf32(acc[mf][nf], af[mf], bf[nf]);
        }
    }

    // epilogue: bias + relu
    #pragma unroll
    for (int mf = 0; mf < 2; ++mf) {
        const int r0 = rowBase + wm * 32 + mf * 16 + (lane >> 2);
        #pragma unroll
        for (int nf = 0; nf < 8; ++nf) {
            const int c0 = colBase + wn * 64 + nf * 8 + (lane & 3) * 2;
            const float bz0 = bias[c0], bz1 = bias[c0 + 1];
            float2 v0, v1;
            v0.x = fmaxf(acc[mf][nf][0] + bz0, 0.f);
            v0.y = fmaxf(acc[mf][nf][1] + bz1, 0.f);
            v1.x = fmaxf(acc[mf][nf][2] + bz0, 0.f);
            v1.y = fmaxf(acc[mf][nf][3] + bz1, 0.f);
            *(float2*)(C + (size_t)r0 * ldc + c0)       = v0;
            *(float2*)(C + (size_t)(r0 + 8) * ldc + c0) = v1;
        }
    }
}

// ================= TF32 attention =================
// Block = (b,h) x 32-row q tile. Scores [32][512] materialized in smem.
#define QS_LD 132   // qs[r][d]  (A of QK^T)    stride%32==4
#define KS_LD 132   // ts[s][d]  as K (B n-major) stride%32==4
#define VS_LD 136   // ts[s][d]  as V (B k-major) stride%32==8
#define SS_LD 516   // ss[r][s]  stride%32==4 (A of PV, plain rows otherwise)
#define ATTN_SMEM ((32*QS_LD + 64*VS_LD + 32*SS_LD) * 4)

__global__ void __launch_bounds__(256)
attn_tf32(const float* __restrict__ Q, const float* __restrict__ KV,
          float* __restrict__ O)
{
    extern __shared__ float sm[];
    float* qs = sm;                             // [32][QS_LD]
    float* ts = sm + 32 * QS_LD;                // [64][VS_LD] (K or V tile)
    float* ss = sm + 32 * QS_LD + 64 * VS_LD;   // [32][SS_LD]

    const int tid  = threadIdx.x;
    const int lane = tid & 31;
    const int warp = tid >> 5;
    const int bh = blockIdx.y;
    const int b = bh >> 3, h = bh & 7;
    const int rt = blockIdx.x;
    const float scale = 0.08838834764831845f;   // 1/sqrt(128)

    const float* qg = Q  + ((size_t)(b * 512 + rt * 32)) * 1024 + h * 128;
    const float* kg = KV + ((size_t)(b * 512)) * 2048 + h * 128;
    const float* vg = kg + 1024;
    float*       og = O  + ((size_t)(b * 512 + rt * 32)) * 1024 + h * 128;

    // ---- load Q (pre-scaled, tf32-rounded) ----
    for (int s = tid; s < 1024; s += 256) {
        int r = s >> 5, c = (s & 31) * 4;
        float4 v = *(const float4*)(qg + (size_t)r * 1024 + c);
        qs[r * QS_LD + c + 0] = f2tf_f(v.x * scale);
        qs[r * QS_LD + c + 1] = f2tf_f(v.y * scale);
        qs[r * QS_LD + c + 2] = f2tf_f(v.z * scale);
        qs[r * QS_LD + c + 3] = f2tf_f(v.w * scale);
    }

    const int wm = warp & 1;   // 2 warps along q-rows (16 each)
    const int wn = warp >> 1;  // 4 warps along the other dim

    // ---- scores: Q @ K^T ----
    for (int st = 0; st < 8; ++st) {
        __syncthreads();
        for (int s = tid; s < 2048; s += 256) {
            int r = s >> 5, c = (s & 31) * 4;
            float4 v = *(const float4*)(kg + (size_t)(st * 64 + r) * 2048 + c);
            ts[r * KS_LD + c + 0] = f2tf_f(v.x);
            ts[r * KS_LD + c + 1] = f2tf_f(v.y);
            ts[r * KS_LD + c + 2] = f2tf_f(v.z);
            ts[r * KS_LD + c + 3] = f2tf_f(v.w);
        }
        __syncthreads();

        float acc[2][4] = {};
        #pragma unroll 4
        for (int kb = 0; kb < 128; kb += 8) {
            unsigned af[4], bf[2][2];
            const int m0 = wm * 16 + (lane >> 2);
            const int kk = kb + (lane & 3);
            af[0] = __float_as_uint(qs[m0 * QS_LD + kk]);
            af[1] = __float_as_uint(qs[(m0 + 8) * QS_LD + kk]);
            af[2] = __float_as_uint(qs[m0 * QS_LD + kk + 4]);
            af[3] = __float_as_uint(qs[(m0 + 8) * QS_LD + kk + 4]);
            #pragma unroll
            for (int nf = 0; nf < 2; ++nf) {
                const int n0 = wn * 16 + nf * 8 + (lane >> 2);
                bf[nf][0] = __float_as_uint(ts[n0 * KS_LD + kk]);
                bf[nf][1] = __float_as_uint(ts[n0 * KS_LD + kk + 4]);
            }
            mma_tf32(acc[0], af, bf[0]);
            mma_tf32(acc[1], af, bf[1]);
        }
        // write scores
        const int r0 = wm * 16 + (lane >> 2);
        #pragma unroll
        for (int nf = 0; nf < 2; ++nf) {
            const int c0 = st * 64 + wn * 16 + nf * 8 + (lane & 3) * 2;
            ss[r0 * SS_LD + c0]           = acc[nf][0];
            ss[r0 * SS_LD + c0 + 1]       = acc[nf][1];
            ss[(r0 + 8) * SS_LD + c0]     = acc[nf][2];
            ss[(r0 + 8) * SS_LD + c0 + 1] = acc[nf][3];
        }
    }
    __syncthreads();

    // ---- softmax (warp per 4 rows), probs tf32-rounded ----
    for (int rr = 0; rr < 4; ++rr) {
        const int row = warp * 4 + rr;
        float m = -1e30f;
        for (int c = lane; c < 512; c += 32) m = fmaxf(m, ss[row * SS_LD + c]);
        #pragma unroll
        for (int o = 16; o; o >>= 1) m = fmaxf(m, __shfl_xor_sync(0xffffffffu, m, o));
        float sum = 0.f;
        for (int c = lane; c < 512; c += 32) {
            float e = __expf(ss[row * SS_LD + c] - m);
            ss[row * SS_LD + c] = e;
            sum += e;
        }
        #pragma unroll
        for (int o = 16; o; o >>= 1) sum += __shfl_xor_sync(0xffffffffu, sum, o);
        float inv = 1.f / sum;
        for (int c = lane; c < 512; c += 32)
            ss[row * SS_LD + c] = f2tf_f(ss[row * SS_LD + c] * inv);
    }
    __syncthreads();

    // ---- P @ V ----
    float oacc[4][4] = {};
    for (int st = 0; st < 8; ++st) {
        if (st) __syncthreads();
        for (int s = tid; s < 2048; s += 256) {
            int r = s >> 5, c = (s & 31) * 4;
            float4 v = *(const float4*)(vg + (size_t)(st * 64 + r) * 2048 + c);
            ts[r * VS_LD + c + 0] = f2tf_f(v.x);
            ts[r * VS_LD + c + 1] = f2tf_f(v.y);
            ts[r * VS_LD + c + 2] = f2tf_f(v.z);
            ts[r * VS_LD + c + 3] = f2tf_f(v.w);
        }
        __syncthreads();

        #pragma unroll 4
        for (int kb = 0; kb < 64; kb += 8) {
            unsigned af[4], bf[4][2];
            const int m0 = wm * 16 + (lane >> 2);
            const int kk = st * 64 + kb + (lane & 3);
            af[0] = __float_as_uint(ss[m0 * SS_LD + kk]);
            af[1] = __float_as_uint(ss[(m0 + 8) * SS_LD + kk]);
            af[2] = __float_as_uint(ss[m0 * SS_LD + kk + 4]);
            af[3] = __float_as_uint(ss[(m0 + 8) * SS_LD + kk + 4]);
            const int kl = kb + (lane & 3);
            #pragma unroll
            for (int nf = 0; nf < 4; ++nf) {
                const int n0 = wn * 32 + nf * 8 + (lane >> 2);
                bf[nf][0] = __float_as_uint(ts[kl * VS_LD + n0]);
                bf[nf][1] = __float_as_uint(ts[(kl + 4) * VS_LD + n0]);
            }
            #pragma unroll
            for (int nf = 0; nf < 4; ++nf)
                mma_tf32(oacc[nf], af, bf[nf]);
        }
    }

    // ---- store O ----
    const int r0 = wm * 16 + (lane >> 2);
    #pragma unroll
    for (int nf = 0; nf < 4; ++nf) {
        const int c0 = wn * 32 + nf * 8 + (lane & 3) * 2;
        float2 v0 = {oacc[nf][0], oacc[nf][1]};
        float2 v1 = {oacc[nf][2], oacc[nf][3]};
        *(float2*)(og + (size_t)r0 * 1024 + c0)       = v0;
        *(float2*)(og + (size_t)(r0 + 8) * 1024 + c0) = v1;
    }
}

// ---------------- launch ----------------
extern "C" void kernel_launch(void* const* d_in, const int* in_sizes, int n_in,
                              void* d_out, int out_size)
{
    const float* src   = (const float*)d_in[0];
    const float* tgt   = (const float*)d_in[1];
    const float* W_src = (const float*)d_in[2];
    const float* b_src = (const float*)d_in[3];
    const float* W_tgt = (const float*)d_in[4];
    const float* b_tgt = (const float*)d_in[5];
    const float* W_out = (const float*)d_in[6];
    const float* b_out = (const float*)d_in[7];
    float* out = (float*)d_out;

    float *src_tran, *tgt_query, *tgt_update;
    cudaGetSymbolAddress((void**)&src_tran,  g_src_tran);
    cudaGetSymbolAddress((void**)&tgt_query, g_tgt_query);
    cudaGetSymbolAddress((void**)&tgt_update, g_tgt_update);

    cudaFuncSetAttribute(attn_tf32,
                         cudaFuncAttributeMaxDynamicSharedMemorySize, ATTN_SMEM);

    dim3 blk(256);

    // GEMM1: src_tran = relu(src @ W_src + b_src)   [8192,512]x[512,2048]
    gemm_tf32_relu<<<dim3(2048 / BN, 8192 / BM), blk>>>(
        src, 512, 512, nullptr, 0, W_src, 2048, b_src, src_tran, 2048, 512);

    // GEMM2: tgt_query = relu(tgt @ W_tgt + b_tgt)  [8192,512]x[512,1024]
    gemm_tf32_relu<<<dim3(1024 / BN, 8192 / BM), blk>>>(
        tgt, 512, 512, nullptr, 0, W_tgt, 1024, b_tgt, tgt_query, 1024, 512);

    // attention
    attn_tf32<<<dim3(16, 128), blk, ATTN_SMEM>>>(tgt_query, src_tran, tgt_update);

    // GEMM3: out = relu([tgt | tgt_update] @ W_out + b_out)  [8192,1536]x[1536,1024]
    gemm_tf32_relu<<<dim3(1024 / BN, 8192 / BM), blk>>>(
        tgt, 512, 512, tgt_update, 1024, W_out, 1024, b_out, out, 1024, 1536);
}

// round 4
// speedup vs baseline: 12.2741x; 2.7080x over previous
#include <cuda_runtime.h>
#include <cuda_fp16.h>
#include <math.h>

// ---------------- scratch (static device globals; no allocation) ----------------
__device__ __half g_srctran_h[16*512*2048];  // relu(src@W_src+b), fp16 (K | V)
__device__ __half g_q_h     [16*512*1024];   // relu(tgt@W_tgt+b), fp16
__device__ __half g_upd_h   [16*512*1024];   // attention output, fp16
__device__ __half g_vt      [16*8*128*512];  // V transposed [b][h][d][s]
__device__ __half g_src_h   [16*512*512];
__device__ __half g_tgt_h   [16*512*512];
__device__ __half g_wsrc_t  [2048*512];      // W_src^T  [N][K]
__device__ __half g_wtgt_t  [1024*512];      // W_tgt^T
__device__ __half g_wout_t  [1024*1536];     // W_out^T

// ---------------- PTX helpers ----------------
__device__ __forceinline__ void cp_async16(void* smem, const void* gmem) {
    unsigned s = (unsigned)__cvta_generic_to_shared(smem);
    asm volatile("cp.async.cg.shared.global [%0], [%1], 16;\n" :: "r"(s), "l"(gmem));
}
__device__ __forceinline__ void cp_commit() { asm volatile("cp.async.commit_group;\n"); }
template<int N> __device__ __forceinline__ void cp_wait() {
    asm volatile("cp.async.wait_group %0;\n" :: "n"(N));
}
__device__ __forceinline__ void mma_f16(float (&d)[4], const unsigned (&a)[4],
                                        const unsigned (&b)[2]) {
    asm volatile(
        "mma.sync.aligned.m16n8k16.row.col.f32.f16.f16.f32 "
        "{%0,%1,%2,%3}, {%4,%5,%6,%7}, {%8,%9}, {%0,%1,%2,%3};\n"
        : "+f"(d[0]), "+f"(d[1]), "+f"(d[2]), "+f"(d[3])
        : "r"(a[0]), "r"(a[1]), "r"(a[2]), "r"(a[3]), "r"(b[0]), "r"(b[1]));
}
__device__ __forceinline__ unsigned lds32(const __half* p) {
    return *(const unsigned*)p;
}

// ---------------- pre-pass: fp32 -> fp16 ----------------
__global__ void cvt_f2h(const float4* __restrict__ in, __half2* __restrict__ out, int n4) {
    int i = blockIdx.x * blockDim.x + threadIdx.x;
    if (i < n4) {
        float4 v = in[i];
        out[2*i]   = __floats2half2_rn(v.x, v.y);
        out[2*i+1] = __floats2half2_rn(v.z, v.w);
    }
}

// transpose + convert: in fp32 [K][N] -> out fp16 [N][K]
__global__ void transcvt(const float* __restrict__ in, __half* __restrict__ out,
                         int K, int N) {
    __shared__ __half tile[32][33];
    int n0 = blockIdx.x * 32, k0 = blockIdx.y * 32;
    int tx = threadIdx.x, ty = threadIdx.y;
    #pragma unroll
    for (int j = 0; j < 4; ++j)
        tile[ty + 8*j][tx] = __float2half_rn(in[(size_t)(k0 + ty + 8*j) * N + n0 + tx]);
    __syncthreads();
    #pragma unroll
    for (int j = 0; j < 4; ++j)
        out[(size_t)(n0 + ty + 8*j) * K + k0 + tx] = tile[tx][ty + 8*j];
}

// V transpose: g_srctran_h [b][s][2048] (val = cols 1024+h*128+d) -> g_vt [b][h][d][s]
__global__ void vtrans(const __half* __restrict__ in, __half* __restrict__ out) {
    __shared__ __half tile[32][33];
    int bh = blockIdx.y;                 // b*8+h
    int b = bh >> 3, h = bh & 7;
    int s0 = (blockIdx.x >> 2) * 32, d0 = (blockIdx.x & 3) * 32;
    int tx = threadIdx.x, ty = threadIdx.y;
    #pragma unroll
    for (int j = 0; j < 4; ++j)
        tile[ty + 8*j][tx] =
            in[((size_t)(b * 512 + s0 + ty + 8*j)) * 2048 + 1024 + h * 128 + d0 + tx];
    __syncthreads();
    #pragma unroll
    for (int j = 0; j < 4; ++j)
        out[((size_t)bh * 128 + d0 + ty + 8*j) * 512 + s0 + tx] = tile[tx][ty + 8*j];
}

// ================= fp16 GEMM: C = relu(A @ Bt^T + bias) =================
// A fp16 [M][K] virtual-concat (A0 first kA0 cols, then A1). Bt fp16 [N][K].
#define BM 128
#define BN 128
#define BK 32
#define GLD 40                       // smem leading dim (halfs); banks conflict-free
#define STAGE_H (2 * BM * GLD)       // As + Bs per stage, in halfs
#define GEMM_SMEM (3 * STAGE_H * 2)  // bytes

template<typename OutT>
__global__ void __launch_bounds__(256)
gemm_h(const __half* __restrict__ A0, int lda0, int kA0,
       const __half* __restrict__ A1, int lda1,
       const __half* __restrict__ Bt,
       const float* __restrict__ bias,
       OutT* __restrict__ C, int ldc, int K)
{
    extern __shared__ __half sm[];
    const int tid  = threadIdx.x;
    const int lane = tid & 31;
    const int warp = tid >> 5;
    const int wm   = warp & 3;    // 4 warps x 32 rows
    const int wn   = warp >> 2;   // 2 warps x 64 cols
    const int rowBase = blockIdx.y * BM;
    const int colBase = blockIdx.x * BN;

    const int T = K / BK;

    auto stage = [&](int t) {
        const int buf = t % 3;
        __half* as = sm + buf * STAGE_H;
        __half* bs = as + BM * GLD;
        const int k0 = t * BK;
        const __half* Ap; int lda, kk;
        if (k0 < kA0) { Ap = A0; lda = lda0; kk = k0; }
        else          { Ap = A1; lda = lda1; kk = k0 - kA0; }
        #pragma unroll
        for (int j = 0; j < 2; ++j) {
            int e = tid + j * 256;
            int row = e >> 2, sg = e & 3;
            cp_async16(as + row * GLD + sg * 8,
                       Ap + (size_t)(rowBase + row) * lda + kk + sg * 8);
        }
        #pragma unroll
        for (int j = 0; j < 2; ++j) {
            int e = tid + j * 256;
            int row = e >> 2, sg = e & 3;
            cp_async16(bs + row * GLD + sg * 8,
                       Bt + (size_t)(colBase + row) * K + k0 + sg * 8);
        }
        cp_commit();
    };

    float acc[2][8][4] = {};

    stage(0);
    stage(1);

    for (int t = 0; t < T; ++t) {
        cp_wait<1>();
        __syncthreads();
        if (t + 2 < T) stage(t + 2);

        const __half* as = sm + (t % 3) * STAGE_H;
        const __half* bs = as + BM * GLD;
        #pragma unroll
        for (int kb = 0; kb < 2; ++kb) {
            const int kk = kb * 16 + 2 * (lane & 3);
            unsigned af[2][4], bf[8][2];
            const int m0 = wm * 32 + (lane >> 2);
            #pragma unroll
            for (int mf = 0; mf < 2; ++mf) {
                const __half* p = as + (m0 + mf * 16) * GLD + kk;
                af[mf][0] = lds32(p);
                af[mf][1] = lds32(p + 8 * GLD);
                af[mf][2] = lds32(p + 8);
                af[mf][3] = lds32(p + 8 * GLD + 8);
            }
            const int n0 = wn * 64 + (lane >> 2);
            #pragma unroll
            for (int nf = 0; nf < 8; ++nf) {
                const __half* p = bs + (n0 + nf * 8) * GLD + kk;
                bf[nf][0] = lds32(p);
                bf[nf][1] = lds32(p + 8);
            }
            #pragma unroll
            for (int mf = 0; mf < 2; ++mf)
                #pragma unroll
                for (int nf = 0; nf < 8; ++nf)
                    mma_f16(acc[mf][nf], af[mf], bf[nf]);
        }
    }

    // epilogue: bias + relu
    #pragma unroll
    for (int mf = 0; mf < 2; ++mf) {
        const int r0 = rowBase + wm * 32 + mf * 16 + (lane >> 2);
        #pragma unroll
        for (int nf = 0; nf < 8; ++nf) {
            const int c0 = colBase + wn * 64 + nf * 8 + (lane & 3) * 2;
            const float bz0 = bias[c0], bz1 = bias[c0 + 1];
            float v00 = fmaxf(acc[mf][nf][0] + bz0, 0.f);
            float v01 = fmaxf(acc[mf][nf][1] + bz1, 0.f);
            float v10 = fmaxf(acc[mf][nf][2] + bz0, 0.f);
            float v11 = fmaxf(acc[mf][nf][3] + bz1, 0.f);
            if constexpr (sizeof(OutT) == 2) {
                *(__half2*)((__half*)C + (size_t)r0 * ldc + c0) =
                    __floats2half2_rn(v00, v01);
                *(__half2*)((__half*)C + (size_t)(r0 + 8) * ldc + c0) =
                    __floats2half2_rn(v10, v11);
            } else {
                *(float2*)((float*)C + (size_t)r0 * ldc + c0)       = make_float2(v00, v01);
                *(float2*)((float*)C + (size_t)(r0 + 8) * ldc + c0) = make_float2(v10, v11);
            }
        }
    }
}

// ================= fp16 attention =================
// Block = (b,h) x 32 q-rows. K tiles [64][136], V tiles [128][72] double-buffered.
#define QLD 136
#define KLD 136
#define VLD 72
#define SLD 520
#define KVBUF 9216   // halfs per kv buffer: max(64*136, 128*72)
// smem halfs: qs 32*136=4352, kv 2*9216=18432, ss 32*520=16640  -> 39424 halfs
#define ATTN_SMEM (39424 * 2)

__global__ void __launch_bounds__(256)
attn_h(const __half* __restrict__ Q, const __half* __restrict__ Kg,
       const __half* __restrict__ Vt, __half* __restrict__ O)
{
    extern __shared__ __half sm[];
    __half* qs = sm;                 // [32][QLD]
    __half* kv = sm + 32 * QLD;      // 2 buffers of KVBUF
    __half* ss = kv + 2 * KVBUF;     // [32][SLD]

    const int tid  = threadIdx.x;
    const int lane = tid & 31;
    const int warp = tid >> 5;
    const int bh = blockIdx.y;
    const int b = bh >> 3, h = bh & 7;
    const int rt = blockIdx.x;
    const float scale = 0.08838834764831845f;   // 1/sqrt(128)

    const __half* qg  = Q  + ((size_t)(b * 512 + rt * 32)) * 1024 + h * 128;
    const __half* kg  = Kg + ((size_t)(b * 512)) * 2048 + h * 128;
    const __half* vtg = Vt + (size_t)bh * 128 * 512;
    __half*       og  = O  + ((size_t)(b * 512 + rt * 32)) * 1024 + h * 128;

    // K tile: 64 rows x 128 halfs -> 64*16 = 1024 cp_async16 ops
    auto issue_K = [&](int st) {
        __half* dst = kv + (st & 1) * KVBUF;
        #pragma unroll
        for (int j = 0; j < 4; ++j) {
            int e = tid + j * 256;
            int row = e >> 4, sg = e & 15;
            cp_async16(dst + row * KLD + sg * 8,
                       kg + (size_t)(st * 64 + row) * 2048 + sg * 8);
        }
        cp_commit();
    };
    // V tile: 128 rows (d) x 64 halfs (s) -> 128*8 = 1024 ops
    auto issue_V = [&](int st) {
        __half* dst = kv + (st & 1) * KVBUF;
        #pragma unroll
        for (int j = 0; j < 4; ++j) {
            int e = tid + j * 256;
            int row = e >> 3, sg = e & 7;
            cp_async16(dst + row * VLD + sg * 8,
                       vtg + (size_t)row * 512 + st * 64 + sg * 8);
        }
        cp_commit();
    };

    // ---- issue Q + K0 as one group ----
    {
        #pragma unroll
        for (int j = 0; j < 2; ++j) {
            int e = tid + j * 256;
            int row = e >> 4, sg = e & 15;
            cp_async16(qs + row * QLD + sg * 8,
                       qg + (size_t)row * 1024 + sg * 8);
        }
        issue_K(0);   // commits Q+K0 together
    }

    const int wm = warp & 1;    // 2 x 16 q-rows
    const int wn = warp >> 1;   // 4 x (16 score cols | 32 d cols)

    cp_wait<0>();
    __syncthreads();

    // ---- preload Q fragments (k-invariant) ----
    unsigned af[8][4];
    {
        const int m0 = wm * 16 + (lane >> 2);
        #pragma unroll
        for (int kb = 0; kb < 8; ++kb) {
            const __half* p = qs + m0 * QLD + kb * 16 + 2 * (lane & 3);
            af[kb][0] = lds32(p);
            af[kb][1] = lds32(p + 8 * QLD);
            af[kb][2] = lds32(p + 8);
            af[kb][3] = lds32(p + 8 * QLD + 8);
        }
    }

    // ---- scores: Q @ K^T ----
    for (int st = 0; st < 8; ++st) {
        if (st) { cp_wait<0>(); __syncthreads(); }
        if (st < 7) issue_K(st + 1);

        const __half* ks = kv + (st & 1) * KVBUF;
        float acc[2][4] = {};
        #pragma unroll
        for (int kb = 0; kb < 8; ++kb) {
            const int kk = kb * 16 + 2 * (lane & 3);
            unsigned bf[2][2];
            #pragma unroll
            for (int nf = 0; nf < 2; ++nf) {
                const int n0 = wn * 16 + nf * 8 + (lane >> 2);
                const __half* p = ks + n0 * KLD + kk;
                bf[nf][0] = lds32(p);
                bf[nf][1] = lds32(p + 8);
            }
            mma_f16(acc[0], af[kb], bf[0]);
            mma_f16(acc[1], af[kb], bf[1]);
        }
        const int r0 = wm * 16 + (lane >> 2);
        #pragma unroll
        for (int nf = 0; nf < 2; ++nf) {
            const int c0 = st * 64 + wn * 16 + nf * 8 + (lane & 3) * 2;
            *(__half2*)(ss + r0 * SLD + c0)       = __floats2half2_rn(acc[nf][0], acc[nf][1]);
            *(__half2*)(ss + (r0 + 8) * SLD + c0) = __floats2half2_rn(acc[nf][2], acc[nf][3]);
        }
    }

    issue_V(0);        // overlap V0 copy with softmax
    __syncthreads();   // scores visible

    // ---- softmax (warp per 4 rows); scale folded into exp ----
    for (int rr = 0; rr < 4; ++rr) {
        const int row = warp * 4 + rr;
        float m = -1e30f;
        for (int c = lane; c < 512; c += 32)
            m = fmaxf(m, __half2float(ss[row * SLD + c]));
        #pragma unroll
        for (int o = 16; o; o >>= 1) m = fmaxf(m, __shfl_xor_sync(0xffffffffu, m, o));
        float sum = 0.f;
        for (int c = lane; c < 512; c += 32) {
            float e = __expf((__half2float(ss[row * SLD + c]) - m) * scale);
            ss[row * SLD + c] = __float2half_rn(e);
            sum += e;
        }
        #pragma unroll
        for (int o = 16; o; o >>= 1) sum += __shfl_xor_sync(0xffffffffu, sum, o);
        float inv = 1.f / sum;
        for (int c = lane; c < 512; c += 32)
            ss[row * SLD + c] = __float2half_rn(__half2float(ss[row * SLD + c]) * inv);
    }
    __syncthreads();

    // ---- P @ V ----
    float oacc[4][4] = {};
    for (int st = 0; st < 8; ++st) {
        cp_wait<0>();
        __syncthreads();
        if (st < 7) issue_V(st + 1);

        const __half* vs = kv + (st & 1) * KVBUF;
        #pragma unroll
        for (int kb = 0; kb < 4; ++kb) {
            unsigned pa[4], bf[4][2];
            const int m0 = wm * 16 + (lane >> 2);
            const int kcol = st * 64 + kb * 16 + 2 * (lane & 3);
            const __half* p = ss + m0 * SLD + kcol;
            pa[0] = lds32(p);
            pa[1] = lds32(p + 8 * SLD);
            pa[2] = lds32(p + 8);
            pa[3] = lds32(p + 8 * SLD + 8);
            const int kk = kb * 16 + 2 * (lane & 3);
            #pragma unroll
            for (int nf = 0; nf < 4; ++nf) {
                const int n0 = wn * 32 + nf * 8 + (lane >> 2);
                const __half* q = vs + n0 * VLD + kk;
                bf[nf][0] = lds32(q);
                bf[nf][1] = lds32(q + 8);
            }
            #pragma unroll
            for (int nf = 0; nf < 4; ++nf)
                mma_f16(oacc[nf], pa, bf[nf]);
        }
    }

    // ---- store O (fp16) ----
    const int r0 = wm * 16 + (lane >> 2);
    #pragma unroll
    for (int nf = 0; nf < 4; ++nf) {
        const int c0 = wn * 32 + nf * 8 + (lane & 3) * 2;
        *(__half2*)(og + (size_t)r0 * 1024 + c0) =
            __floats2half2_rn(oacc[nf][0], oacc[nf][1]);
        *(__half2*)(og + (size_t)(r0 + 8) * 1024 + c0) =
            __floats2half2_rn(oacc[nf][2], oacc[nf][3]);
    }
}

// ---------------- launch ----------------
extern "C" void kernel_launch(void* const* d_in, const int* in_sizes, int n_in,
                              void* d_out, int out_size)
{
    const float* src   = (const float*)d_in[0];
    const float* tgt   = (const float*)d_in[1];
    const float* W_src = (const float*)d_in[2];
    const float* b_src = (const float*)d_in[3];
    const float* W_tgt = (const float*)d_in[4];
    const float* b_tgt = (const float*)d_in[5];
    const float* W_out = (const float*)d_in[6];
    const float* b_out = (const float*)d_in[7];
    float* out = (float*)d_out;

    __half *srctran, *qh, *upd, *vt, *srch, *tgth, *wsrc_t, *wtgt_t, *wout_t;
    cudaGetSymbolAddress((void**)&srctran, g_srctran_h);
    cudaGetSymbolAddress((void**)&qh,      g_q_h);
    cudaGetSymbolAddress((void**)&upd,     g_upd_h);
    cudaGetSymbolAddress((void**)&vt,      g_vt);
    cudaGetSymbolAddress((void**)&srch,    g_src_h);
    cudaGetSymbolAddress((void**)&tgth,    g_tgt_h);
    cudaGetSymbolAddress((void**)&wsrc_t,  g_wsrc_t);
    cudaGetSymbolAddress((void**)&wtgt_t,  g_wtgt_t);
    cudaGetSymbolAddress((void**)&wout_t,  g_wout_t);

    cudaFuncSetAttribute(gemm_h<__half>,
                         cudaFuncAttributeMaxDynamicSharedMemorySize, GEMM_SMEM);
    cudaFuncSetAttribute(gemm_h<float>,
                         cudaFuncAttributeMaxDynamicSharedMemorySize, GEMM_SMEM);
    cudaFuncSetAttribute(attn_h,
                         cudaFuncAttributeMaxDynamicSharedMemorySize, ATTN_SMEM);

    // ---- pre-pass conversions ----
    const int n_st = 16 * 512 * 512;      // src / tgt elements
    cvt_f2h<<<(n_st/4 + 255)/256, 256>>>((const float4*)src, (__half2*)srch, n_st/4);
    cvt_f2h<<<(n_st/4 + 255)/256, 256>>>((const float4*)tgt, (__half2*)tgth, n_st/4);
    transcvt<<<dim3(2048/32, 512/32),  dim3(32,8)>>>(W_src, wsrc_t, 512, 2048);
    transcvt<<<dim3(1024/32, 512/32),  dim3(32,8)>>>(W_tgt, wtgt_t, 512, 1024);
    transcvt<<<dim3(1024/32, 1536/32), dim3(32,8)>>>(W_out, wout_t, 1536, 1024);

    dim3 blk(256);

    // GEMM1: srctran = relu(src @ W_src + b)   [8192,512]x[512,2048]
    gemm_h<__half><<<dim3(2048/BN, 8192/BM), blk, GEMM_SMEM>>>(
        srch, 512, 512, srch, 512, wsrc_t, b_src, srctran, 2048, 512);

    // GEMM2: qh = relu(tgt @ W_tgt + b)        [8192,512]x[512,1024]
    gemm_h<__half><<<dim3(1024/BN, 8192/BM), blk, GEMM_SMEM>>>(
        tgth, 512, 512, tgth, 512, wtgt_t, b_tgt, qh, 1024, 512);

    // V transpose for attention
    vtrans<<<dim3(64, 128), dim3(32,8)>>>(srctran, vt);

    // attention
    attn_h<<<dim3(16, 128), blk, ATTN_SMEM>>>(qh, srctran, vt, upd);

    // GEMM3: out = relu([tgt | upd] @ W_out + b)  [8192,1536]x[1536,1024]
    gemm_h<float><<<dim3(1024/BN, 8192/BM), blk, GEMM_SMEM>>>(
        tgth, 512, 512, upd, 1024, wout_t, b_out, out, 1024, 1536);
}

// round 5
// speedup vs baseline: 13.6634x; 1.1132x over previous
#include <cuda_runtime.h>
#include <cuda_fp16.h>
#include <math.h>

// ---------------- scratch (static device globals; no allocation) ----------------
__device__ __half g_srctran_h[16*512*2048];  // relu(src@W_src+b), fp16 (K | V)
__device__ __half g_q_h     [16*512*1024];   // relu(tgt@W_tgt+b), fp16
__device__ __half g_upd_h   [16*512*1024];   // attention output, fp16
__device__ __half g_vt      [16*8*128*512];  // V transposed [b][h][d][s]
__device__ __half g_src_h   [16*512*512];
__device__ __half g_tgt_h   [16*512*512];
__device__ __half g_wsrc_t  [2048*512];      // W_src^T  [N][K]
__device__ __half g_wtgt_t  [1024*512];      // W_tgt^T
__device__ __half g_wout_t  [1024*1536];     // W_out^T

// ---------------- PTX helpers ----------------
__device__ __forceinline__ void cp_async16(void* smem, const void* gmem) {
    unsigned s = (unsigned)__cvta_generic_to_shared(smem);
    asm volatile("cp.async.cg.shared.global [%0], [%1], 16;\n" :: "r"(s), "l"(gmem));
}
__device__ __forceinline__ void cp_commit() { asm volatile("cp.async.commit_group;\n"); }
template<int N> __device__ __forceinline__ void cp_wait() {
    asm volatile("cp.async.wait_group %0;\n" :: "n"(N));
}
__device__ __forceinline__ void mma_f16(float (&d)[4], const unsigned (&a)[4],
                                        const unsigned (&b)[2]) {
    asm volatile(
        "mma.sync.aligned.m16n8k16.row.col.f32.f16.f16.f32 "
        "{%0,%1,%2,%3}, {%4,%5,%6,%7}, {%8,%9}, {%0,%1,%2,%3};\n"
        : "+f"(d[0]), "+f"(d[1]), "+f"(d[2]), "+f"(d[3])
        : "r"(a[0]), "r"(a[1]), "r"(a[2]), "r"(a[3]), "r"(b[0]), "r"(b[1]));
}
__device__ __forceinline__ void ldsm_x4(unsigned &r0, unsigned &r1,
                                        unsigned &r2, unsigned &r3,
                                        const __half* p) {
    unsigned a = (unsigned)__cvta_generic_to_shared(p);
    asm volatile("ldmatrix.sync.aligned.m8n8.x4.shared.b16 {%0,%1,%2,%3}, [%4];\n"
                 : "=r"(r0), "=r"(r1), "=r"(r2), "=r"(r3) : "r"(a));
}

// ---------------- pre-pass: fp32 -> fp16 ----------------
__global__ void cvt_f2h(const float4* __restrict__ in, __half2* __restrict__ out, int n4) {
    int i = blockIdx.x * blockDim.x + threadIdx.x;
    if (i < n4) {
        float4 v = in[i];
        out[2*i]   = __floats2half2_rn(v.x, v.y);
        out[2*i+1] = __floats2half2_rn(v.z, v.w);
    }
}

// transpose + convert: in fp32 [K][N] -> out fp16 [N][K]
__global__ void transcvt(const float* __restrict__ in, __half* __restrict__ out,
                         int K, int N) {
    __shared__ __half tile[32][33];
    int n0 = blockIdx.x * 32, k0 = blockIdx.y * 32;
    int tx = threadIdx.x, ty = threadIdx.y;
    #pragma unroll
    for (int j = 0; j < 4; ++j)
        tile[ty + 8*j][tx] = __float2half_rn(in[(size_t)(k0 + ty + 8*j) * N + n0 + tx]);
    __syncthreads();
    #pragma unroll
    for (int j = 0; j < 4; ++j)
        out[(size_t)(n0 + ty + 8*j) * K + k0 + tx] = tile[tx][ty + 8*j];
}

// V transpose: g_srctran_h [b][s][2048] (val = cols 1024+h*128+d) -> g_vt [b][h][d][s]
__global__ void vtrans(const __half* __restrict__ in, __half* __restrict__ out) {
    __shared__ __half tile[32][33];
    int bh = blockIdx.y;                 // b*8+h
    int b = bh >> 3, h = bh & 7;
    int s0 = (blockIdx.x >> 2) * 32, d0 = (blockIdx.x & 3) * 32;
    int tx = threadIdx.x, ty = threadIdx.y;
    #pragma unroll
    for (int j = 0; j < 4; ++j)
        tile[ty + 8*j][tx] =
            in[((size_t)(b * 512 + s0 + ty + 8*j)) * 2048 + 1024 + h * 128 + d0 + tx];
    __syncthreads();
    #pragma unroll
    for (int j = 0; j < 4; ++j)
        out[((size_t)bh * 128 + d0 + ty + 8*j) * 512 + s0 + tx] = tile[tx][ty + 8*j];
}

// ================= fp16 GEMM: C = relu(A @ Bt^T + bias) =================
// A fp16 [M][K] virtual-concat (A0 first kA0 cols, then A1). Bt fp16 [N][K].
#define BM 128
#define BN 128
#define BK 32
#define GLD 40                       // smem leading dim (halfs); conflict-free
#define STAGE_H (2 * BM * GLD)       // As + Bs per stage, in halfs
#define GEMM_SMEM (3 * STAGE_H * 2)  // bytes

template<typename OutT>
__global__ void __launch_bounds__(256)
gemm_h(const __half* __restrict__ A0, int lda0, int kA0,
       const __half* __restrict__ A1, int lda1,
       const __half* __restrict__ Bt,
       const float* __restrict__ bias,
       OutT* __restrict__ C, int ldc, int K)
{
    extern __shared__ __half sm[];
    const int tid  = threadIdx.x;
    const int lane = tid & 31;
    const int warp = tid >> 5;
    const int wm   = warp & 3;    // 4 warps x 32 rows
    const int wn   = warp >> 2;   // 2 warps x 64 cols
    const int rowBase = blockIdx.y * BM;
    const int colBase = blockIdx.x * BN;

    const int T = K / BK;

    // ldmatrix lane-address components
    const int lmA_row = lane & 15;               // + m0
    const int lmA_col = (lane >> 4) << 3;        // 0 or 8
    const int lmB_row = (lane & 7) + ((lane >> 4) << 3);
    const int lmB_col = lane & 8;

    auto stage = [&](int t) {
        const int buf = t % 3;
        __half* as = sm + buf * STAGE_H;
        __half* bs = as + BM * GLD;
        const int k0 = t * BK;
        const __half* Ap; int lda, kk;
        if (k0 < kA0) { Ap = A0; lda = lda0; kk = k0; }
        else          { Ap = A1; lda = lda1; kk = k0 - kA0; }
        #pragma unroll
        for (int j = 0; j < 2; ++j) {
            int e = tid + j * 256;
            int row = e >> 2, sg = e & 3;
            cp_async16(as + row * GLD + sg * 8,
                       Ap + (size_t)(rowBase + row) * lda + kk + sg * 8);
        }
        #pragma unroll
        for (int j = 0; j < 2; ++j) {
            int e = tid + j * 256;
            int row = e >> 2, sg = e & 3;
            cp_async16(bs + row * GLD + sg * 8,
                       Bt + (size_t)(colBase + row) * K + k0 + sg * 8);
        }
        cp_commit();
    };

    float acc[2][8][4] = {};

    stage(0);
    stage(1);

    for (int t = 0; t < T; ++t) {
        cp_wait<1>();
        __syncthreads();
        if (t + 2 < T) stage(t + 2);

        const __half* as = sm + (t % 3) * STAGE_H;
        const __half* bs = as + BM * GLD;
        #pragma unroll
        for (int kb = 0; kb < 2; ++kb) {
            const int kk = kb * 16;
            unsigned af[2][4], bf[8][2];
            #pragma unroll
            for (int mf = 0; mf < 2; ++mf)
                ldsm_x4(af[mf][0], af[mf][1], af[mf][2], af[mf][3],
                        as + (wm * 32 + mf * 16 + lmA_row) * GLD + kk + lmA_col);
            #pragma unroll
            for (int g = 0; g < 4; ++g)
                ldsm_x4(bf[2*g][0], bf[2*g][1], bf[2*g+1][0], bf[2*g+1][1],
                        bs + (wn * 64 + g * 16 + lmB_row) * GLD + kk + lmB_col);
            #pragma unroll
            for (int mf = 0; mf < 2; ++mf)
                #pragma unroll
                for (int nf = 0; nf < 8; ++nf)
                    mma_f16(acc[mf][nf], af[mf], bf[nf]);
        }
    }

    // epilogue: bias + relu
    #pragma unroll
    for (int mf = 0; mf < 2; ++mf) {
        const int r0 = rowBase + wm * 32 + mf * 16 + (lane >> 2);
        #pragma unroll
        for (int nf = 0; nf < 8; ++nf) {
            const int c0 = colBase + wn * 64 + nf * 8 + (lane & 3) * 2;
            const float bz0 = bias[c0], bz1 = bias[c0 + 1];
            float v00 = fmaxf(acc[mf][nf][0] + bz0, 0.f);
            float v01 = fmaxf(acc[mf][nf][1] + bz1, 0.f);
            float v10 = fmaxf(acc[mf][nf][2] + bz0, 0.f);
            float v11 = fmaxf(acc[mf][nf][3] + bz1, 0.f);
            if constexpr (sizeof(OutT) == 2) {
                *(__half2*)((__half*)C + (size_t)r0 * ldc + c0) =
                    __floats2half2_rn(v00, v01);
                *(__half2*)((__half*)C + (size_t)(r0 + 8) * ldc + c0) =
                    __floats2half2_rn(v10, v11);
            } else {
                *(float2*)((float*)C + (size_t)r0 * ldc + c0)       = make_float2(v00, v01);
                *(float2*)((float*)C + (size_t)(r0 + 8) * ldc + c0) = make_float2(v10, v11);
            }
        }
    }
}

// ================= fp16 attention =================
// Block = (b,h) x 32 q-rows. K tiles [64][136], V tiles [128][72] double-buffered.
#define QLD 136
#define KLD 136
#define VLD 72
#define SLD 520
#define KVBUF 9216   // halfs per kv buffer: max(64*136, 128*72)
#define ATTN_SMEM (39424 * 2)

__global__ void __launch_bounds__(256)
attn_h(const __half* __restrict__ Q, const __half* __restrict__ Kg,
       const __half* __restrict__ Vt, __half* __restrict__ O)
{
    extern __shared__ __half sm[];
    __half* qs = sm;                 // [32][QLD]
    __half* kv = sm + 32 * QLD;      // 2 buffers of KVBUF
    __half* ss = kv + 2 * KVBUF;     // [32][SLD]

    const int tid  = threadIdx.x;
    const int lane = tid & 31;
    const int warp = tid >> 5;
    const int bh = blockIdx.y;
    const int b = bh >> 3, h = bh & 7;
    const int rt = blockIdx.x;
    const float scale = 0.08838834764831845f;   // 1/sqrt(128)

    const __half* qg  = Q  + ((size_t)(b * 512 + rt * 32)) * 1024 + h * 128;
    const __half* kg  = Kg + ((size_t)(b * 512)) * 2048 + h * 128;
    const __half* vtg = Vt + (size_t)bh * 128 * 512;
    __half*       og  = O  + ((size_t)(b * 512 + rt * 32)) * 1024 + h * 128;

    const int lmA_row = lane & 15;
    const int lmA_col = (lane >> 4) << 3;
    const int lmB_row = (lane & 7) + ((lane >> 4) << 3);
    const int lmB_col = lane & 8;

    // K tile: 64 rows x 128 halfs -> 1024 cp_async16 ops
    auto issue_K = [&](int st) {
        __half* dst = kv + (st & 1) * KVBUF;
        #pragma unroll
        for (int j = 0; j < 4; ++j) {
            int e = tid + j * 256;
            int row = e >> 4, sg = e & 15;
            cp_async16(dst + row * KLD + sg * 8,
                       kg + (size_t)(st * 64 + row) * 2048 + sg * 8);
        }
        cp_commit();
    };
    // V tile: 128 rows (d) x 64 halfs (s) -> 1024 ops
    auto issue_V = [&](int st) {
        __half* dst = kv + (st & 1) * KVBUF;
        #pragma unroll
        for (int j = 0; j < 4; ++j) {
            int e = tid + j * 256;
            int row = e >> 3, sg = e & 7;
            cp_async16(dst + row * VLD + sg * 8,
                       vtg + (size_t)row * 512 + st * 64 + sg * 8);
        }
        cp_commit();
    };

    // ---- issue Q + K0 as one group ----
    {
        #pragma unroll
        for (int j = 0; j < 2; ++j) {
            int e = tid + j * 256;
            int row = e >> 4, sg = e & 15;
            cp_async16(qs + row * QLD + sg * 8,
                       qg + (size_t)row * 1024 + sg * 8);
        }
        issue_K(0);   // commits Q+K0 together
    }

    const int wm = warp & 1;    // 2 x 16 q-rows
    const int wn = warp >> 1;   // 4 x (16 score cols | 32 d cols)

    cp_wait<0>();
    __syncthreads();

    // ---- preload Q fragments (k-invariant) ----
    unsigned af[8][4];
    #pragma unroll
    for (int kb = 0; kb < 8; ++kb)
        ldsm_x4(af[kb][0], af[kb][1], af[kb][2], af[kb][3],
                qs + (wm * 16 + lmA_row) * QLD + kb * 16 + lmA_col);

    // ---- scores: Q @ K^T ----
    for (int st = 0; st < 8; ++st) {
        if (st) { cp_wait<0>(); __syncthreads(); }
        if (st < 7) issue_K(st + 1);

        const __half* ks = kv + (st & 1) * KVBUF;
        float acc[2][4] = {};
        #pragma unroll
        for (int kb = 0; kb < 8; ++kb) {
            unsigned bf[2][2];
            ldsm_x4(bf[0][0], bf[0][1], bf[1][0], bf[1][1],
                    ks + (wn * 16 + lmB_row) * KLD + kb * 16 + lmB_col);
            mma_f16(acc[0], af[kb], bf[0]);
            mma_f16(acc[1], af[kb], bf[1]);
        }
        const int r0 = wm * 16 + (lane >> 2);
        #pragma unroll
        for (int nf = 0; nf < 2; ++nf) {
            const int c0 = st * 64 + wn * 16 + nf * 8 + (lane & 3) * 2;
            *(__half2*)(ss + r0 * SLD + c0)       = __floats2half2_rn(acc[nf][0], acc[nf][1]);
            *(__half2*)(ss + (r0 + 8) * SLD + c0) = __floats2half2_rn(acc[nf][2], acc[nf][3]);
        }
    }

    issue_V(0);        // overlap V0 copy with softmax
    __syncthreads();   // scores visible

    // ---- softmax (warp per 4 rows), half2-vectorized; scale folded into exp ----
    for (int rr = 0; rr < 4; ++rr) {
        const int row = warp * 4 + rr;
        __half2* rp = (__half2*)(ss + row * SLD);
        float m = -1e30f;
        #pragma unroll
        for (int c = lane; c < 256; c += 32) {
            float2 v = __half22float2(rp[c]);
            m = fmaxf(m, fmaxf(v.x, v.y));
        }
        #pragma unroll
        for (int o = 16; o; o >>= 1) m = fmaxf(m, __shfl_xor_sync(0xffffffffu, m, o));
        float sum = 0.f;
        #pragma unroll
        for (int c = lane; c < 256; c += 32) {
            float2 v = __half22float2(rp[c]);
            float e0 = __expf((v.x - m) * scale);
            float e1 = __expf((v.y - m) * scale);
            rp[c] = __floats2half2_rn(e0, e1);
            sum += e0 + e1;
        }
        #pragma unroll
        for (int o = 16; o; o >>= 1) sum += __shfl_xor_sync(0xffffffffu, sum, o);
        float inv = 1.f / sum;
        #pragma unroll
        for (int c = lane; c < 256; c += 32) {
            float2 v = __half22float2(rp[c]);
            rp[c] = __floats2half2_rn(v.x * inv, v.y * inv);
        }
    }
    __syncthreads();

    // ---- P @ V ----
    float oacc[4][4] = {};
    for (int st = 0; st < 8; ++st) {
        cp_wait<0>();
        __syncthreads();
        if (st < 7) issue_V(st + 1);

        const __half* vs = kv + (st & 1) * KVBUF;
        #pragma unroll
        for (int kb = 0; kb < 4; ++kb) {
            unsigned pa[4], bf[4][2];
            ldsm_x4(pa[0], pa[1], pa[2], pa[3],
                    ss + (wm * 16 + lmA_row) * SLD + st * 64 + kb * 16 + lmA_col);
            #pragma unroll
            for (int g = 0; g < 2; ++g)
                ldsm_x4(bf[2*g][0], bf[2*g][1], bf[2*g+1][0], bf[2*g+1][1],
                        vs + (wn * 32 + g * 16 + lmB_row) * VLD + kb * 16 + lmB_col);
            #pragma unroll
            for (int nf = 0; nf < 4; ++nf)
                mma_f16(oacc[nf], pa, bf[nf]);
        }
    }

    // ---- store O (fp16) ----
    const int r0 = wm * 16 + (lane >> 2);
    #pragma unroll
    for (int nf = 0; nf < 4; ++nf) {
        const int c0 = wn * 32 + nf * 8 + (lane & 3) * 2;
        *(__half2*)(og + (size_t)r0 * 1024 + c0) =
            __floats2half2_rn(oacc[nf][0], oacc[nf][1]);
        *(__half2*)(og + (size_t)(r0 + 8) * 1024 + c0) =
            __floats2half2_rn(oacc[nf][2], oacc[nf][3]);
    }
}

// ---------------- launch ----------------
extern "C" void kernel_launch(void* const* d_in, const int* in_sizes, int n_in,
                              void* d_out, int out_size)
{
    const float* src   = (const float*)d_in[0];
    const float* tgt   = (const float*)d_in[1];
    const float* W_src = (const float*)d_in[2];
    const float* b_src = (const float*)d_in[3];
    const float* W_tgt = (const float*)d_in[4];
    const float* b_tgt = (const float*)d_in[5];
    const float* W_out = (const float*)d_in[6];
    const float* b_out = (const float*)d_in[7];
    float* out = (float*)d_out;

    __half *srctran, *qh, *upd, *vt, *srch, *tgth, *wsrc_t, *wtgt_t, *wout_t;
    cudaGetSymbolAddress((void**)&srctran, g_srctran_h);
    cudaGetSymbolAddress((void**)&qh,      g_q_h);
    cudaGetSymbolAddress((void**)&upd,     g_upd_h);
    cudaGetSymbolAddress((void**)&vt,      g_vt);
    cudaGetSymbolAddress((void**)&srch,    g_src_h);
    cudaGetSymbolAddress((void**)&tgth,    g_tgt_h);
    cudaGetSymbolAddress((void**)&wsrc_t,  g_wsrc_t);
    cudaGetSymbolAddress((void**)&wtgt_t,  g_wtgt_t);
    cudaGetSymbolAddress((void**)&wout_t,  g_wout_t);

    cudaFuncSetAttribute(gemm_h<__half>,
                         cudaFuncAttributeMaxDynamicSharedMemorySize, GEMM_SMEM);
    cudaFuncSetAttribute(gemm_h<float>,
                         cudaFuncAttributeMaxDynamicSharedMemorySize, GEMM_SMEM);
    cudaFuncSetAttribute(attn_h,
                         cudaFuncAttributeMaxDynamicSharedMemorySize, ATTN_SMEM);

    // ---- pre-pass conversions ----
    const int n_st = 16 * 512 * 512;      // src / tgt elements
    cvt_f2h<<<(n_st/4 + 255)/256, 256>>>((const float4*)src, (__half2*)srch, n_st/4);
    cvt_f2h<<<(n_st/4 + 255)/256, 256>>>((const float4*)tgt, (__half2*)tgth, n_st/4);
    transcvt<<<dim3(2048/32, 512/32),  dim3(32,8)>>>(W_src, wsrc_t, 512, 2048);
    transcvt<<<dim3(1024/32, 512/32),  dim3(32,8)>>>(W_tgt, wtgt_t, 512, 1024);
    transcvt<<<dim3(1024/32, 1536/32), dim3(32,8)>>>(W_out, wout_t, 1536, 1024);

    dim3 blk(256);

    // GEMM1: srctran = relu(src @ W_src + b)   [8192,512]x[512,2048]
    gemm_h<__half><<<dim3(2048/BN, 8192/BM), blk, GEMM_SMEM>>>(
        srch, 512, 512, srch, 512, wsrc_t, b_src, srctran, 2048, 512);

    // GEMM2: qh = relu(tgt @ W_tgt + b)        [8192,512]x[512,1024]
    gemm_h<__half><<<dim3(1024/BN, 8192/BM), blk, GEMM_SMEM>>>(
        tgth, 512, 512, tgth, 512, wtgt_t, b_tgt, qh, 1024, 512);

    // V transpose for attention
    vtrans<<<dim3(64, 128), dim3(32,8)>>>(srctran, vt);

    // attention
    attn_h<<<dim3(16, 128), blk, ATTN_SMEM>>>(qh, srctran, vt, upd);

    // GEMM3: out = relu([tgt | upd] @ W_out + b)  [8192,1536]x[1536,1024]
    gemm_h<float><<<dim3(1024/BN, 8192/BM), blk, GEMM_SMEM>>>(
        tgth, 512, 512, upd, 1024, wout_t, b_out, out, 1024, 1536);
}

// round 7
// speedup vs baseline: 13.9466x; 1.0207x over previous
#include <cuda_runtime.h>
#include <cuda_fp16.h>
#include <math.h>

// ---------------- scratch (static device globals; no allocation) ----------------
__device__ __half g_srctran_h[16*512*2048];  // relu(src@W_src+b), fp16 (K | V)
__device__ __half g_q_h     [16*512*1024];   // relu(tgt@W_tgt+b), fp16
__device__ __half g_upd_h   [16*512*1024];   // attention output, fp16
__device__ __half g_src_h   [16*512*512];
__device__ __half g_tgt_h   [16*512*512];
__device__ __half g_wsrc_t  [2048*512];      // W_src^T  [N][K]
__device__ __half g_wtgt_t  [1024*512];      // W_tgt^T
__device__ __half g_wout_t  [1024*1536];     // W_out^T

// ---------------- PTX helpers ----------------
__device__ __forceinline__ void cp_async16(void* smem, const void* gmem) {
    unsigned s = (unsigned)__cvta_generic_to_shared(smem);
    asm volatile("cp.async.cg.shared.global [%0], [%1], 16;\n" :: "r"(s), "l"(gmem));
}
__device__ __forceinline__ void cp_commit() { asm volatile("cp.async.commit_group;\n"); }
template<int N> __device__ __forceinline__ void cp_wait() {
    asm volatile("cp.async.wait_group %0;\n" :: "n"(N));
}
__device__ __forceinline__ void mma_f16(float (&d)[4], const unsigned (&a)[4],
                                        const unsigned (&b)[2]) {
    asm volatile(
        "mma.sync.aligned.m16n8k16.row.col.f32.f16.f16.f32 "
        "{%0,%1,%2,%3}, {%4,%5,%6,%7}, {%8,%9}, {%0,%1,%2,%3};\n"
        : "+f"(d[0]), "+f"(d[1]), "+f"(d[2]), "+f"(d[3])
        : "r"(a[0]), "r"(a[1]), "r"(a[2]), "r"(a[3]), "r"(b[0]), "r"(b[1]));
}
__device__ __forceinline__ void ldsm_x4(unsigned &r0, unsigned &r1,
                                        unsigned &r2, unsigned &r3,
                                        const __half* p) {
    unsigned a = (unsigned)__cvta_generic_to_shared(p);
    asm volatile("ldmatrix.sync.aligned.m8n8.x4.shared.b16 {%0,%1,%2,%3}, [%4];\n"
                 : "=r"(r0), "=r"(r1), "=r"(r2), "=r"(r3) : "r"(a));
}
__device__ __forceinline__ void ldsm_x4_t(unsigned &r0, unsigned &r1,
                                          unsigned &r2, unsigned &r3,
                                          const __half* p) {
    unsigned a = (unsigned)__cvta_generic_to_shared(p);
    asm volatile("ldmatrix.sync.aligned.m8n8.x4.trans.shared.b16 {%0,%1,%2,%3}, [%4];\n"
                 : "=r"(r0), "=r"(r1), "=r"(r2), "=r"(r3) : "r"(a));
}

// ---------------- pre-pass: fp32 -> fp16 ----------------
__global__ void cvt_f2h(const float4* __restrict__ in, __half2* __restrict__ out, int n4) {
    int i = blockIdx.x * blockDim.x + threadIdx.x;
    if (i < n4) {
        float4 v = in[i];
        out[2*i]   = __floats2half2_rn(v.x, v.y);
        out[2*i+1] = __floats2half2_rn(v.z, v.w);
    }
}

// transpose + convert: in fp32 [K][N] -> out fp16 [N][K]
__global__ void transcvt(const float* __restrict__ in, __half* __restrict__ out,
                         int K, int N) {
    __shared__ __half tile[32][33];
    int n0 = blockIdx.x * 32, k0 = blockIdx.y * 32;
    int tx = threadIdx.x, ty = threadIdx.y;
    #pragma unroll
    for (int j = 0; j < 4; ++j)
        tile[ty + 8*j][tx] = __float2half_rn(in[(size_t)(k0 + ty + 8*j) * N + n0 + tx]);
    __syncthreads();
    #pragma unroll
    for (int j = 0; j < 4; ++j)
        out[(size_t)(n0 + ty + 8*j) * K + k0 + tx] = tile[tx][ty + 8*j];
}

// ================= fp16 GEMM: C = relu(A @ Bt^T + bias) =================
// A fp16 [M][K] virtual-concat (A0 first kA0 cols, then A1). Bt fp16 [N][K].
// CTA tile 128x128, BK=64, 3-stage cp.async pipeline.
#define BM 128
#define BN 128
#define BK 64
#define GLD 72                       // smem leading dim (halfs); conflict-free
#define STAGE_H (2 * BM * GLD)       // As + Bs per stage, in halfs
#define GEMM_SMEM (3 * STAGE_H * 2)  // bytes (110,592)

template<typename OutT>
__global__ void __launch_bounds__(256)
gemm_h(const __half* __restrict__ A0, int lda0, int kA0,
       const __half* __restrict__ A1, int lda1,
       const __half* __restrict__ Bt,
       const float* __restrict__ bias,
       OutT* __restrict__ C, int ldc, int K)
{
    extern __shared__ __half sm[];
    const int tid  = threadIdx.x;
    const int lane = tid & 31;
    const int warp = tid >> 5;
    const int wm   = warp & 3;    // 4 warps x 32 rows
    const int wn   = warp >> 2;   // 2 warps x 64 cols
    const int rowBase = blockIdx.y * BM;
    const int colBase = blockIdx.x * BN;

    const int T = K / BK;

    // ldmatrix lane-address components
    const int lmA_row = lane & 15;
    const int lmA_col = (lane >> 4) << 3;
    const int lmB_row = (lane & 7) + ((lane >> 4) << 3);
    const int lmB_col = lane & 8;

    auto stage = [&](int t) {
        __half* as = sm + (t % 3) * STAGE_H;
        __half* bs = as + BM * GLD;
        const int k0 = t * BK;
        const __half* Ap; int lda, kk;
        if (k0 < kA0) { Ap = A0; lda = lda0; kk = k0; }
        else          { Ap = A1; lda = lda1; kk = k0 - kA0; }
        #pragma unroll
        for (int j = 0; j < 4; ++j) {
            int e = tid + j * 256;
            int row = e >> 3, sg = e & 7;
            cp_async16(as + row * GLD + sg * 8,
                       Ap + (size_t)(rowBase + row) * lda + kk + sg * 8);
        }
        #pragma unroll
        for (int j = 0; j < 4; ++j) {
            int e = tid + j * 256;
            int row = e >> 3, sg = e & 7;
            cp_async16(bs + row * GLD + sg * 8,
                       Bt + (size_t)(colBase + row) * K + k0 + sg * 8);
        }
        cp_commit();
    };

    float acc[2][8][4] = {};

    stage(0);
    stage(1);

    for (int t = 0; t < T; ++t) {
        if (t + 1 < T) cp_wait<1>(); else cp_wait<0>();
        __syncthreads();
        if (t + 2 < T) stage(t + 2);

        const __half* as = sm + (t % 3) * STAGE_H;
        const __half* bs = as + BM * GLD;
        #pragma unroll
        for (int kb = 0; kb < 4; ++kb) {
            const int kk = kb * 16;
            unsigned af[2][4], bf[8][2];
            #pragma unroll
            for (int mf = 0; mf < 2; ++mf)
                ldsm_x4(af[mf][0], af[mf][1], af[mf][2], af[mf][3],
                        as + (wm * 32 + mf * 16 + lmA_row) * GLD + kk + lmA_col);
            #pragma unroll
            for (int g = 0; g < 4; ++g)
                ldsm_x4(bf[2*g][0], bf[2*g][1], bf[2*g+1][0], bf[2*g+1][1],
                        bs + (wn * 64 + g * 16 + lmB_row) * GLD + kk + lmB_col);
            #pragma unroll
            for (int mf = 0; mf < 2; ++mf)
                #pragma unroll
                for (int nf = 0; nf < 8; ++nf)
                    mma_f16(acc[mf][nf], af[mf], bf[nf]);
        }
    }

    // epilogue: bias + relu
    #pragma unroll
    for (int mf = 0; mf < 2; ++mf) {
        const int r0 = rowBase + wm * 32 + mf * 16 + (lane >> 2);
        #pragma unroll
        for (int nf = 0; nf < 8; ++nf) {
            const int c0 = colBase + wn * 64 + nf * 8 + (lane & 3) * 2;
            const float bz0 = bias[c0], bz1 = bias[c0 + 1];
            float v00 = fmaxf(acc[mf][nf][0] + bz0, 0.f);
            float v01 = fmaxf(acc[mf][nf][1] + bz1, 0.f);
            float v10 = fmaxf(acc[mf][nf][2] + bz0, 0.f);
            float v11 = fmaxf(acc[mf][nf][3] + bz1, 0.f);
            if constexpr (sizeof(OutT) == 2) {
                *(__half2*)((__half*)C + (size_t)r0 * ldc + c0) =
                    __floats2half2_rn(v00, v01);
                *(__half2*)((__half*)C + (size_t)(r0 + 8) * ldc + c0) =
                    __floats2half2_rn(v10, v11);
            } else {
                *(float2*)((float*)C + (size_t)r0 * ldc + c0)       = make_float2(v00, v01);
                *(float2*)((float*)C + (size_t)(r0 + 8) * ldc + c0) = make_float2(v10, v11);
            }
        }
    }
}

// ================= fp16 attention =================
// Block = (b,h) x 32 q-rows. K and V tiles both [64 s][128 d] (LD 136),
// double-buffered; V B-fragments via ldmatrix.x4.trans (no pre-transpose).
#define QLD 136
#define KLD 136
#define SLD 520
#define KVBUF (64 * KLD)   // 8704 halfs
// smem halfs: qs 32*136=4352, kv 2*8704=17408, ss 32*520=16640 -> 38400
#define ATTN_SMEM (38400 * 2)

__global__ void __launch_bounds__(256)
attn_h(const __half* __restrict__ Q, const __half* __restrict__ KVg,
       __half* __restrict__ O)
{
    extern __shared__ __half sm[];
    __half* qs = sm;                 // [32][QLD]
    __half* kv = sm + 32 * QLD;      // 2 buffers of KVBUF
    __half* ss = kv + 2 * KVBUF;     // [32][SLD]

    const int tid  = threadIdx.x;
    const int lane = tid & 31;
    const int warp = tid >> 5;
    const int bh = blockIdx.y;
    const int b = bh >> 3, h = bh & 7;
    const int rt = blockIdx.x;
    const float scale = 0.08838834764831845f;   // 1/sqrt(128)

    const __half* qg = Q   + ((size_t)(b * 512 + rt * 32)) * 1024 + h * 128;
    const __half* kg = KVg + ((size_t)(b * 512)) * 2048 + h * 128;
    const __half* vg = kg + 1024;
    __half*       og = O   + ((size_t)(b * 512 + rt * 32)) * 1024 + h * 128;

    const int lmA_row = lane & 15;
    const int lmA_col = (lane >> 4) << 3;
    const int lmB_row = (lane & 7) + ((lane >> 4) << 3);
    const int lmB_col = lane & 8;

    // K/V tile: 64 rows x 128 halfs -> 1024 cp_async16 ops
    auto issue_KV = [&](const __half* base, int st) {
        __half* dst = kv + (st & 1) * KVBUF;
        #pragma unroll
        for (int j = 0; j < 4; ++j) {
            int e = tid + j * 256;
            int row = e >> 4, sg = e & 15;
            cp_async16(dst + row * KLD + sg * 8,
                       base + (size_t)(st * 64 + row) * 2048 + sg * 8);
        }
        cp_commit();
    };

    // ---- issue Q + K0 as one group ----
    {
        #pragma unroll
        for (int j = 0; j < 2; ++j) {
            int e = tid + j * 256;
            int row = e >> 4, sg = e & 15;
            cp_async16(qs + row * QLD + sg * 8,
                       qg + (size_t)row * 1024 + sg * 8);
        }
        issue_KV(kg, 0);   // commits Q+K0 together
    }

    const int wm = warp & 1;    // 2 x 16 q-rows
    const int wn = warp >> 1;   // 4 x (16 score cols | 32 d cols)

    cp_wait<0>();
    __syncthreads();

    // ---- preload Q fragments (k-invariant) ----
    unsigned af[8][4];
    #pragma unroll
    for (int kb = 0; kb < 8; ++kb)
        ldsm_x4(af[kb][0], af[kb][1], af[kb][2], af[kb][3],
                qs + (wm * 16 + lmA_row) * QLD + kb * 16 + lmA_col);

    // ---- scores: Q @ K^T ----
    for (int st = 0; st < 8; ++st) {
        if (st) { cp_wait<0>(); __syncthreads(); }
        if (st < 7) issue_KV(kg, st + 1);

        const __half* ks = kv + (st & 1) * KVBUF;
        float acc[2][4] = {};
        #pragma unroll
        for (int kb = 0; kb < 8; ++kb) {
            unsigned bf[2][2];
            ldsm_x4(bf[0][0], bf[0][1], bf[1][0], bf[1][1],
                    ks + (wn * 16 + lmB_row) * KLD + kb * 16 + lmB_col);
            mma_f16(acc[0], af[kb], bf[0]);
            mma_f16(acc[1], af[kb], bf[1]);
        }
        const int r0 = wm * 16 + (lane >> 2);
        #pragma unroll
        for (int nf = 0; nf < 2; ++nf) {
            const int c0 = st * 64 + wn * 16 + nf * 8 + (lane & 3) * 2;
            *(__half2*)(ss + r0 * SLD + c0)       = __floats2half2_rn(acc[nf][0], acc[nf][1]);
            *(__half2*)(ss + (r0 + 8) * SLD + c0) = __floats2half2_rn(acc[nf][2], acc[nf][3]);
        }
    }

    issue_KV(vg, 0);   // overlap V0 copy with softmax
    __syncthreads();   // scores visible

    // ---- softmax (warp per 4 rows), half2-vectorized; scale folded into exp ----
    for (int rr = 0; rr < 4; ++rr) {
        const int row = warp * 4 + rr;
        __half2* rp = (__half2*)(ss + row * SLD);
        float m = -1e30f;
        #pragma unroll
        for (int c = lane; c < 256; c += 32) {
            float2 v = __half22float2(rp[c]);
            m = fmaxf(m, fmaxf(v.x, v.y));
        }
        #pragma unroll
        for (int o = 16; o; o >>= 1) m = fmaxf(m, __shfl_xor_sync(0xffffffffu, m, o));
        float sum = 0.f;
        #pragma unroll
        for (int c = lane; c < 256; c += 32) {
            float2 v = __half22float2(rp[c]);
            float e0 = __expf((v.x - m) * scale);
            float e1 = __expf((v.y - m) * scale);
            rp[c] = __floats2half2_rn(e0, e1);
            sum += e0 + e1;
        }
        #pragma unroll
        for (int o = 16; o; o >>= 1) sum += __shfl_xor_sync(0xffffffffu, sum, o);
        float inv = 1.f / sum;
        #pragma unroll
        for (int c = lane; c < 256; c += 32) {
            float2 v = __half22float2(rp[c]);
            rp[c] = __floats2half2_rn(v.x * inv, v.y * inv);
        }
    }
    __syncthreads();

    // ---- P @ V ----  (V staged [s][d]; B-frags via ldmatrix.trans)
    float oacc[4][4] = {};
    for (int st = 0; st < 8; ++st) {
        cp_wait<0>();
        __syncthreads();
        if (st < 7) issue_KV(vg, st + 1);

        const __half* vs = kv + (st & 1) * KVBUF;
        #pragma unroll
        for (int kb = 0; kb < 4; ++kb) {
            unsigned pa[4], bf[4][2];
            ldsm_x4(pa[0], pa[1], pa[2], pa[3],
                    ss + (wm * 16 + lmA_row) * SLD + st * 64 + kb * 16 + lmA_col);
            #pragma unroll
            for (int g = 0; g < 2; ++g)
                ldsm_x4_t(bf[2*g][0], bf[2*g][1], bf[2*g+1][0], bf[2*g+1][1],
                          vs + (kb * 16 + lmA_row) * KLD + wn * 32 + g * 16 + lmA_col);
            #pragma unroll
            for (int nf = 0; nf < 4; ++nf)
                mma_f16(oacc[nf], pa, bf[nf]);
        }
    }

    // ---- store O (fp16) ----
    const int r0 = wm * 16 + (lane >> 2);
    #pragma unroll
    for (int nf = 0; nf < 4; ++nf) {
        const int c0 = wn * 32 + nf * 8 + (lane & 3) * 2;
        *(__half2*)(og + (size_t)r0 * 1024 + c0) =
            __floats2half2_rn(oacc[nf][0], oacc[nf][1]);
        *(__half2*)(og + (size_t)(r0 + 8) * 1024 + c0) =
            __floats2half2_rn(oacc[nf][2], oacc[nf][3]);
    }
}

// ---------------- launch ----------------
extern "C" void kernel_launch(void* const* d_in, const int* in_sizes, int n_in,
                              void* d_out, int out_size)
{
    const float* src   = (const float*)d_in[0];
    const float* tgt   = (const float*)d_in[1];
    const float* W_src = (const float*)d_in[2];
    const float* b_src = (const float*)d_in[3];
    const float* W_tgt = (const float*)d_in[4];
    const float* b_tgt = (const float*)d_in[5];
    const float* W_out = (const float*)d_in[6];
    const float* b_out = (const float*)d_in[7];
    float* out = (float*)d_out;

    __half *srctran, *qh, *upd, *srch, *tgth, *wsrc_t, *wtgt_t, *wout_t;
    cudaGetSymbolAddress((void**)&srctran, g_srctran_h);
    cudaGetSymbolAddress((void**)&qh,      g_q_h);
    cudaGetSymbolAddress((void**)&upd,     g_upd_h);
    cudaGetSymbolAddress((void**)&srch,    g_src_h);
    cudaGetSymbolAddress((void**)&tgth,    g_tgt_h);
    cudaGetSymbolAddress((void**)&wsrc_t,  g_wsrc_t);
    cudaGetSymbolAddress((void**)&wtgt_t,  g_wtgt_t);
    cudaGetSymbolAddress((void**)&wout_t,  g_wout_t);

    cudaFuncSetAttribute(gemm_h<__half>,
                         cudaFuncAttributeMaxDynamicSharedMemorySize, GEMM_SMEM);
    cudaFuncSetAttribute(gemm_h<float>,
                         cudaFuncAttributeMaxDynamicSharedMemorySize, GEMM_SMEM);
    cudaFuncSetAttribute(attn_h,
                         cudaFuncAttributeMaxDynamicSharedMemorySize, ATTN_SMEM);

    // ---- pre-pass conversions ----
    const int n_st = 16 * 512 * 512;      // src / tgt elements
    cvt_f2h<<<(n_st/4 + 255)/256, 256>>>((const float4*)src, (__half2*)srch, n_st/4);
    cvt_f2h<<<(n_st/4 + 255)/256, 256>>>((const float4*)tgt, (__half2*)tgth, n_st/4);
    transcvt<<<dim3(2048/32, 512/32),  dim3(32,8)>>>(W_src, wsrc_t, 512, 2048);
    transcvt<<<dim3(1024/32, 512/32),  dim3(32,8)>>>(W_tgt, wtgt_t, 512, 1024);
    transcvt<<<dim3(1024/32, 1536/32), dim3(32,8)>>>(W_out, wout_t, 1536, 1024);

    dim3 blk(256);

    // GEMM1: srctran = relu(src @ W_src + b)   [8192,512]x[512,2048]
    gemm_h<__half><<<dim3(2048/BN, 8192/BM), blk, GEMM_SMEM>>>(
        srch, 512, 512, srch, 512, wsrc_t, b_src, srctran, 2048, 512);

    // GEMM2: qh = relu(tgt @ W_tgt + b)        [8192,512]x[512,1024]
    gemm_h<__half><<<dim3(1024/BN, 8192/BM), blk, GEMM_SMEM>>>(
        tgth, 512, 512, tgth, 512, wtgt_t, b_tgt, qh, 1024, 512);

    // attention (V read directly from srctran, ldmatrix.trans)
    attn_h<<<dim3(16, 128), blk, ATTN_SMEM>>>(qh, srctran, upd);

    // GEMM3: out = relu([tgt | upd] @ W_out + b)  [8192,1536]x[1536,1024]
    gemm_h<float><<<dim3(1024/BN, 8192/BM), blk, GEMM_SMEM>>>(
        tgth, 512, 512, upd, 1024, wout_t, b_out, out, 1024, 1536);
}

// round 8
// speedup vs baseline: 15.4451x; 1.1074x over previous
#include <cuda_runtime.h>
#include <cuda_fp16.h>
#include <math.h>

// ---------------- scratch (static device globals; no allocation) ----------------
__device__ __half g_srctran_h[16*512*2048];  // relu(src@W_src+b), fp16 (K | V)
__device__ __half g_q_h     [16*512*1024];   // relu(tgt@W_tgt+b), fp16
__device__ __half g_upd_h   [16*512*1024];   // attention output, fp16
__device__ __half g_src_h   [16*512*512];
__device__ __half g_tgt_h   [16*512*512];
__device__ __half g_wsrc_t  [2048*512];      // W_src^T  [N][K]
__device__ __half g_wtgt_t  [1024*512];      // W_tgt^T
__device__ __half g_wout_t  [1024*1536];     // W_out^T

// ---------------- PTX helpers ----------------
__device__ __forceinline__ void cp_async16(void* smem, const void* gmem) {
    unsigned s = (unsigned)__cvta_generic_to_shared(smem);
    asm volatile("cp.async.cg.shared.global [%0], [%1], 16;\n" :: "r"(s), "l"(gmem));
}
__device__ __forceinline__ void cp_commit() { asm volatile("cp.async.commit_group;\n"); }
template<int N> __device__ __forceinline__ void cp_wait() {
    asm volatile("cp.async.wait_group %0;\n" :: "n"(N));
}
__device__ __forceinline__ void mma_f16(float (&d)[4], const unsigned (&a)[4],
                                        const unsigned (&b)[2]) {
    asm volatile(
        "mma.sync.aligned.m16n8k16.row.col.f32.f16.f16.f32 "
        "{%0,%1,%2,%3}, {%4,%5,%6,%7}, {%8,%9}, {%0,%1,%2,%3};\n"
        : "+f"(d[0]), "+f"(d[1]), "+f"(d[2]), "+f"(d[3])
        : "r"(a[0]), "r"(a[1]), "r"(a[2]), "r"(a[3]), "r"(b[0]), "r"(b[1]));
}
__device__ __forceinline__ void ldsm_x4(unsigned &r0, unsigned &r1,
                                        unsigned &r2, unsigned &r3,
                                        const __half* p) {
    unsigned a = (unsigned)__cvta_generic_to_shared(p);
    asm volatile("ldmatrix.sync.aligned.m8n8.x4.shared.b16 {%0,%1,%2,%3}, [%4];\n"
                 : "=r"(r0), "=r"(r1), "=r"(r2), "=r"(r3) : "r"(a));
}
__device__ __forceinline__ void ldsm_x4_t(unsigned &r0, unsigned &r1,
                                          unsigned &r2, unsigned &r3,
                                          const __half* p) {
    unsigned a = (unsigned)__cvta_generic_to_shared(p);
    asm volatile("ldmatrix.sync.aligned.m8n8.x4.trans.shared.b16 {%0,%1,%2,%3}, [%4];\n"
                 : "=r"(r0), "=r"(r1), "=r"(r2), "=r"(r3) : "r"(a));
}

// ---------------- pre-pass: fp32 -> fp16 ----------------
__global__ void cvt_f2h(const float4* __restrict__ in, __half2* __restrict__ out, int n4) {
    int i = blockIdx.x * blockDim.x + threadIdx.x;
    if (i < n4) {
        float4 v = in[i];
        out[2*i]   = __floats2half2_rn(v.x, v.y);
        out[2*i+1] = __floats2half2_rn(v.z, v.w);
    }
}

// transpose + convert: in fp32 [K][N] -> out fp16 [N][K]
__global__ void transcvt(const float* __restrict__ in, __half* __restrict__ out,
                         int K, int N) {
    __shared__ __half tile[32][33];
    int n0 = blockIdx.x * 32, k0 = blockIdx.y * 32;
    int tx = threadIdx.x, ty = threadIdx.y;
    #pragma unroll
    for (int j = 0; j < 4; ++j)
        tile[ty + 8*j][tx] = __float2half_rn(in[(size_t)(k0 + ty + 8*j) * N + n0 + tx]);
    __syncthreads();
    #pragma unroll
    for (int j = 0; j < 4; ++j)
        out[(size_t)(n0 + ty + 8*j) * K + k0 + tx] = tile[tx][ty + 8*j];
}

// ================= fp16 GEMM: C = relu(A @ Bt^T + bias) =================
// MERGED=true: two independent GEMMs share one grid. Blocks with
// blockIdx.x < nx0 run set0 {A0,Bt0,bias0,C0}, the rest set1. No concat.
// MERGED=false: A is a virtual concat (A0 first kA0 cols, then A1); set0 only.
#define BM 128
#define BN 128
#define BK 64
#define GLD 72                       // smem leading dim (halfs); conflict-free
#define STAGE_H (2 * BM * GLD)       // As + Bs per stage, in halfs
#define GEMM_SMEM (3 * STAGE_H * 2)  // bytes (110,592)

template<typename OutT, bool MERGED>
__global__ void __launch_bounds__(256, 2)
gemm_h(const __half* __restrict__ A0, int lda0, int kA0,
       const __half* __restrict__ A1, int lda1,
       const __half* __restrict__ Bt0, const float* __restrict__ bias0,
       OutT* __restrict__ C0, int ldc0,
       const __half* __restrict__ Bt1, const float* __restrict__ bias1,
       OutT* __restrict__ C1, int ldc1,
       int nx0, int K)
{
    extern __shared__ __half sm[];
    const int tid  = threadIdx.x;
    const int lane = tid & 31;
    const int warp = tid >> 5;
    const int wm   = warp & 3;    // 4 warps x 32 rows
    const int wn   = warp >> 2;   // 2 warps x 64 cols
    const int rowBase = blockIdx.y * BM;

    const bool sel0 = !MERGED || ((int)blockIdx.x < nx0);
    const int colBase = (sel0 ? blockIdx.x : blockIdx.x - nx0) * BN;
    const __half* Bt  = sel0 ? Bt0  : Bt1;
    const float* bias = sel0 ? bias0 : bias1;
    OutT* C           = sel0 ? C0   : C1;
    const int ldc     = sel0 ? ldc0 : ldc1;
    const __half* Am  = sel0 ? A0 : A1;    // MERGED: per-set A
    const int ldam    = sel0 ? lda0 : lda1;

    const int T = K / BK;

    const int lmA_row = lane & 15;
    const int lmA_col = (lane >> 4) << 3;
    const int lmB_row = (lane & 7) + ((lane >> 4) << 3);
    const int lmB_col = lane & 8;

    auto stage = [&](int t) {
        __half* as = sm + (t % 3) * STAGE_H;
        __half* bs = as + BM * GLD;
        const int k0 = t * BK;
        const __half* Ap; int lda, kk;
        if (MERGED)            { Ap = Am; lda = ldam; kk = k0; }
        else if (k0 < kA0)     { Ap = A0; lda = lda0; kk = k0; }
        else                   { Ap = A1; lda = lda1; kk = k0 - kA0; }
        #pragma unroll
        for (int j = 0; j < 4; ++j) {
            int e = tid + j * 256;
            int row = e >> 3, sg = e & 7;
            cp_async16(as + row * GLD + sg * 8,
                       Ap + (size_t)(rowBase + row) * lda + kk + sg * 8);
        }
        #pragma unroll
        for (int j = 0; j < 4; ++j) {
            int e = tid + j * 256;
            int row = e >> 3, sg = e & 7;
            cp_async16(bs + row * GLD + sg * 8,
                       Bt + (size_t)(colBase + row) * K + k0 + sg * 8);
        }
        cp_commit();
    };

    float acc[2][8][4] = {};

    stage(0);
    stage(1);

    for (int t = 0; t < T; ++t) {
        if (t + 1 < T) cp_wait<1>(); else cp_wait<0>();
        __syncthreads();
        if (t + 2 < T) stage(t + 2);

        const __half* as = sm + (t % 3) * STAGE_H;
        const __half* bs = as + BM * GLD;
        #pragma unroll
        for (int kb = 0; kb < 4; ++kb) {
            const int kk = kb * 16;
            unsigned af[2][4], bf[8][2];
            #pragma unroll
            for (int mf = 0; mf < 2; ++mf)
                ldsm_x4(af[mf][0], af[mf][1], af[mf][2], af[mf][3],
                        as + (wm * 32 + mf * 16 + lmA_row) * GLD + kk + lmA_col);
            #pragma unroll
            for (int g = 0; g < 4; ++g)
                ldsm_x4(bf[2*g][0], bf[2*g][1], bf[2*g+1][0], bf[2*g+1][1],
                        bs + (wn * 64 + g * 16 + lmB_row) * GLD + kk + lmB_col);
            #pragma unroll
            for (int mf = 0; mf < 2; ++mf)
                #pragma unroll
                for (int nf = 0; nf < 8; ++nf)
                    mma_f16(acc[mf][nf], af[mf], bf[nf]);
        }
    }

    // epilogue: bias + relu
    #pragma unroll
    for (int mf = 0; mf < 2; ++mf) {
        const int r0 = rowBase + wm * 32 + mf * 16 + (lane >> 2);
        #pragma unroll
        for (int nf = 0; nf < 8; ++nf) {
            const int c0 = colBase + wn * 64 + nf * 8 + (lane & 3) * 2;
            const float bz0 = bias[c0], bz1 = bias[c0 + 1];
            float v00 = fmaxf(acc[mf][nf][0] + bz0, 0.f);
            float v01 = fmaxf(acc[mf][nf][1] + bz1, 0.f);
            float v10 = fmaxf(acc[mf][nf][2] + bz0, 0.f);
            float v11 = fmaxf(acc[mf][nf][3] + bz1, 0.f);
            if constexpr (sizeof(OutT) == 2) {
                *(__half2*)((__half*)C + (size_t)r0 * ldc + c0) =
                    __floats2half2_rn(v00, v01);
                *(__half2*)((__half*)C + (size_t)(r0 + 8) * ldc + c0) =
                    __floats2half2_rn(v10, v11);
            } else {
                *(float2*)((float*)C + (size_t)r0 * ldc + c0)       = make_float2(v00, v01);
                *(float2*)((float*)C + (size_t)(r0 + 8) * ldc + c0) = make_float2(v10, v11);
            }
        }
    }
}

// ================= fp16 attention =================
// Block = (b,h) x 32 q-rows. K and V tiles both [64 s][128 d] (LD 136),
// double-buffered; V B-fragments via ldmatrix.x4.trans.
#define QLD 136
#define KLD 136
#define SLD 520
#define KVBUF (64 * KLD)   // 8704 halfs
#define ATTN_SMEM (38400 * 2)

__global__ void __launch_bounds__(256, 2)
attn_h(const __half* __restrict__ Q, const __half* __restrict__ KVg,
       __half* __restrict__ O)
{
    extern __shared__ __half sm[];
    __half* qs = sm;                 // [32][QLD]
    __half* kv = sm + 32 * QLD;      // 2 buffers of KVBUF
    __half* ss = kv + 2 * KVBUF;     // [32][SLD]

    const int tid  = threadIdx.x;
    const int lane = tid & 31;
    const int warp = tid >> 5;
    const int bh = blockIdx.y;
    const int b = bh >> 3, h = bh & 7;
    const int rt = blockIdx.x;
    const float scale = 0.08838834764831845f;   // 1/sqrt(128)

    const __half* qg = Q   + ((size_t)(b * 512 + rt * 32)) * 1024 + h * 128;
    const __half* kg = KVg + ((size_t)(b * 512)) * 2048 + h * 128;
    const __half* vg = kg + 1024;
    __half*       og = O   + ((size_t)(b * 512 + rt * 32)) * 1024 + h * 128;

    const int lmA_row = lane & 15;
    const int lmA_col = (lane >> 4) << 3;
    const int lmB_row = (lane & 7) + ((lane >> 4) << 3);
    const int lmB_col = lane & 8;

    auto issue_KV = [&](const __half* base, int st) {
        __half* dst = kv + (st & 1) * KVBUF;
        #pragma unroll
        for (int j = 0; j < 4; ++j) {
            int e = tid + j * 256;
            int row = e >> 4, sg = e & 15;
            cp_async16(dst + row * KLD + sg * 8,
                       base + (size_t)(st * 64 + row) * 2048 + sg * 8);
        }
        cp_commit();
    };

    {
        #pragma unroll
        for (int j = 0; j < 2; ++j) {
            int e = tid + j * 256;
            int row = e >> 4, sg = e & 15;
            cp_async16(qs + row * QLD + sg * 8,
                       qg + (size_t)row * 1024 + sg * 8);
        }
        issue_KV(kg, 0);   // commits Q+K0 together
    }

    const int wm = warp & 1;    // 2 x 16 q-rows
    const int wn = warp >> 1;   // 4 x (16 score cols | 32 d cols)

    cp_wait<0>();
    __syncthreads();

    unsigned af[8][4];
    #pragma unroll
    for (int kb = 0; kb < 8; ++kb)
        ldsm_x4(af[kb][0], af[kb][1], af[kb][2], af[kb][3],
                qs + (wm * 16 + lmA_row) * QLD + kb * 16 + lmA_col);

    // ---- scores: Q @ K^T ----
    for (int st = 0; st < 8; ++st) {
        if (st) { cp_wait<0>(); __syncthreads(); }
        if (st < 7) issue_KV(kg, st + 1);

        const __half* ks = kv + (st & 1) * KVBUF;
        float acc[2][4] = {};
        #pragma unroll
        for (int kb = 0; kb < 8; ++kb) {
            unsigned bf[2][2];
            ldsm_x4(bf[0][0], bf[0][1], bf[1][0], bf[1][1],
                    ks + (wn * 16 + lmB_row) * KLD + kb * 16 + lmB_col);
            mma_f16(acc[0], af[kb], bf[0]);
            mma_f16(acc[1], af[kb], bf[1]);
        }
        const int r0 = wm * 16 + (lane >> 2);
        #pragma unroll
        for (int nf = 0; nf < 2; ++nf) {
            const int c0 = st * 64 + wn * 16 + nf * 8 + (lane & 3) * 2;
            *(__half2*)(ss + r0 * SLD + c0)       = __floats2half2_rn(acc[nf][0], acc[nf][1]);
            *(__half2*)(ss + (r0 + 8) * SLD + c0) = __floats2half2_rn(acc[nf][2], acc[nf][3]);
        }
    }

    issue_KV(vg, 0);   // overlap V0 copy with softmax
    __syncthreads();   // scores visible

    // ---- softmax (warp per 4 rows), half2-vectorized; scale folded into exp ----
    for (int rr = 0; rr < 4; ++rr) {
        const int row = warp * 4 + rr;
        __half2* rp = (__half2*)(ss + row * SLD);
        float m = -1e30f;
        #pragma unroll
        for (int c = lane; c < 256; c += 32) {
            float2 v = __half22float2(rp[c]);
            m = fmaxf(m, fmaxf(v.x, v.y));
        }
        #pragma unroll
        for (int o = 16; o; o >>= 1) m = fmaxf(m, __shfl_xor_sync(0xffffffffu, m, o));
        float sum = 0.f;
        #pragma unroll
        for (int c = lane; c < 256; c += 32) {
            float2 v = __half22float2(rp[c]);
            float e0 = __expf((v.x - m) * scale);
            float e1 = __expf((v.y - m) * scale);
            rp[c] = __floats2half2_rn(e0, e1);
            sum += e0 + e1;
        }
        #pragma unroll
        for (int o = 16; o; o >>= 1) sum += __shfl_xor_sync(0xffffffffu, sum, o);
        float inv = 1.f / sum;
        #pragma unroll
        for (int c = lane; c < 256; c += 32) {
            float2 v = __half22float2(rp[c]);
            rp[c] = __floats2half2_rn(v.x * inv, v.y * inv);
        }
    }
    __syncthreads();

    // ---- P @ V ----  (V staged [s][d]; B-frags via ldmatrix.trans)
    float oacc[4][4] = {};
    for (int st = 0; st < 8; ++st) {
        cp_wait<0>();
        __syncthreads();
        if (st < 7) issue_KV(vg, st + 1);

        const __half* vs = kv + (st & 1) * KVBUF;
        #pragma unroll
        for (int kb = 0; kb < 4; ++kb) {
            unsigned pa[4], bf[4][2];
            ldsm_x4(pa[0], pa[1], pa[2], pa[3],
                    ss + (wm * 16 + lmA_row) * SLD + st * 64 + kb * 16 + lmA_col);
            #pragma unroll
            for (int g = 0; g < 2; ++g)
                ldsm_x4_t(bf[2*g][0], bf[2*g][1], bf[2*g+1][0], bf[2*g+1][1],
                          vs + (kb * 16 + lmA_row) * KLD + wn * 32 + g * 16 + lmA_col);
            #pragma unroll
            for (int nf = 0; nf < 4; ++nf)
                mma_f16(oacc[nf], pa, bf[nf]);
        }
    }

    // ---- store O (fp16) ----
    const int r0 = wm * 16 + (lane >> 2);
    #pragma unroll
    for (int nf = 0; nf < 4; ++nf) {
        const int c0 = wn * 32 + nf * 8 + (lane & 3) * 2;
        *(__half2*)(og + (size_t)r0 * 1024 + c0) =
            __floats2half2_rn(oacc[nf][0], oacc[nf][1]);
        *(__half2*)(og + (size_t)(r0 + 8) * 1024 + c0) =
            __floats2half2_rn(oacc[nf][2], oacc[nf][3]);
    }
}

// ---------------- launch ----------------
extern "C" void kernel_launch(void* const* d_in, const int* in_sizes, int n_in,
                              void* d_out, int out_size)
{
    const float* src   = (const float*)d_in[0];
    const float* tgt   = (const float*)d_in[1];
    const float* W_src = (const float*)d_in[2];
    const float* b_src = (const float*)d_in[3];
    const float* W_tgt = (const float*)d_in[4];
    const float* b_tgt = (const float*)d_in[5];
    const float* W_out = (const float*)d_in[6];
    const float* b_out = (const float*)d_in[7];
    float* out = (float*)d_out;

    __half *srctran, *qh, *upd, *srch, *tgth, *wsrc_t, *wtgt_t, *wout_t;
    cudaGetSymbolAddress((void**)&srctran, g_srctran_h);
    cudaGetSymbolAddress((void**)&qh,      g_q_h);
    cudaGetSymbolAddress((void**)&upd,     g_upd_h);
    cudaGetSymbolAddress((void**)&srch,    g_src_h);
    cudaGetSymbolAddress((void**)&tgth,    g_tgt_h);
    cudaGetSymbolAddress((void**)&wsrc_t,  g_wsrc_t);
    cudaGetSymbolAddress((void**)&wtgt_t,  g_wtgt_t);
    cudaGetSymbolAddress((void**)&wout_t,  g_wout_t);

    cudaFuncSetAttribute((const void*)gemm_h<__half, true>,
                         cudaFuncAttributeMaxDynamicSharedMemorySize, GEMM_SMEM);
    cudaFuncSetAttribute((const void*)gemm_h<float, false>,
                         cudaFuncAttributeMaxDynamicSharedMemorySize, GEMM_SMEM);
    cudaFuncSetAttribute((const void*)attn_h,
                         cudaFuncAttributeMaxDynamicSharedMemorySize, ATTN_SMEM);

    // ---- pre-pass conversions ----
    const int n_st = 16 * 512 * 512;      // src / tgt elements
    cvt_f2h<<<(n_st/4 + 255)/256, 256>>>((const float4*)src, (__half2*)srch, n_st/4);
    cvt_f2h<<<(n_st/4 + 255)/256, 256>>>((const float4*)tgt, (__half2*)tgth, n_st/4);
    transcvt<<<dim3(2048/32, 512/32),  dim3(32,8)>>>(W_src, wsrc_t, 512, 2048);
    transcvt<<<dim3(1024/32, 512/32),  dim3(32,8)>>>(W_tgt, wtgt_t, 512, 1024);
    transcvt<<<dim3(1024/32, 1536/32), dim3(32,8)>>>(W_out, wout_t, 1536, 1024);

    dim3 blk(256);

    // GEMM1 + GEMM2 fused into one grid:
    //  set0 (x <  16): srctran = relu(src @ W_src + b)  [8192,512]x[512,2048]
    //  set1 (x >= 16): qh      = relu(tgt @ W_tgt + b)  [8192,512]x[512,1024]
    gemm_h<__half, true><<<dim3(16 + 8, 8192/BM), blk, GEMM_SMEM>>>(
        srch, 512, 512, tgth, 512,
        wsrc_t, b_src, srctran, 2048,
        wtgt_t, b_tgt, qh,      1024,
        16, 512);

    // attention (V read directly from srctran, ldmatrix.trans)
    attn_h<<<dim3(16, 128), blk, ATTN_SMEM>>>(qh, srctran, upd);

    // GEMM3: out = relu([tgt | upd] @ W_out + b)  [8192,1536]x[1536,1024]
    gemm_h<float, false><<<dim3(1024/BN, 8192/BM), blk, GEMM_SMEM>>>(
        tgth, 512, 512, upd, 1024,
        wout_t, b_out, out, 1024,
        nullptr, nullptr, nullptr, 0,
        1024/BN, 1536);
}

// round 9
// speedup vs baseline: 17.9230x; 1.1604x over previous
#include <cuda_runtime.h>
#include <cuda_fp16.h>
#include <math.h>

// ---------------- scratch (static device globals; no allocation) ----------------
__device__ __half g_srctran_h[16*512*2048];  // relu(src@W_src+b), fp16 (K | V)
__device__ __half g_q_h     [16*512*1024];   // relu(tgt@W_tgt+b), fp16
__device__ __half g_upd_h   [16*512*1024];   // attention output, fp16
__device__ __half g_src_h   [16*512*512];
__device__ __half g_tgt_h   [16*512*512];
__device__ __half g_wsrc_t  [2048*512];      // W_src^T  [N][K]
__device__ __half g_wtgt_t  [1024*512];      // W_tgt^T
__device__ __half g_wout_t  [1024*1536];     // W_out^T

// ---------------- PTX helpers ----------------
__device__ __forceinline__ void cp_async16(void* smem, const void* gmem) {
    unsigned s = (unsigned)__cvta_generic_to_shared(smem);
    asm volatile("cp.async.cg.shared.global [%0], [%1], 16;\n" :: "r"(s), "l"(gmem));
}
__device__ __forceinline__ void cp_commit() { asm volatile("cp.async.commit_group;\n"); }
template<int N> __device__ __forceinline__ void cp_wait() {
    asm volatile("cp.async.wait_group %0;\n" :: "n"(N));
}
__device__ __forceinline__ void mma_f16(float (&d)[4], const unsigned (&a)[4],
                                        const unsigned (&b)[2]) {
    asm volatile(
        "mma.sync.aligned.m16n8k16.row.col.f32.f16.f16.f32 "
        "{%0,%1,%2,%3}, {%4,%5,%6,%7}, {%8,%9}, {%0,%1,%2,%3};\n"
        : "+f"(d[0]), "+f"(d[1]), "+f"(d[2]), "+f"(d[3])
        : "r"(a[0]), "r"(a[1]), "r"(a[2]), "r"(a[3]), "r"(b[0]), "r"(b[1]));
}
__device__ __forceinline__ void ldsm_x4(unsigned &r0, unsigned &r1,
                                        unsigned &r2, unsigned &r3,
                                        const __half* p) {
    unsigned a = (unsigned)__cvta_generic_to_shared(p);
    asm volatile("ldmatrix.sync.aligned.m8n8.x4.shared.b16 {%0,%1,%2,%3}, [%4];\n"
                 : "=r"(r0), "=r"(r1), "=r"(r2), "=r"(r3) : "r"(a));
}
__device__ __forceinline__ void ldsm_x4_t(unsigned &r0, unsigned &r1,
                                          unsigned &r2, unsigned &r3,
                                          const __half* p) {
    unsigned a = (unsigned)__cvta_generic_to_shared(p);
    asm volatile("ldmatrix.sync.aligned.m8n8.x4.trans.shared.b16 {%0,%1,%2,%3}, [%4];\n"
                 : "=r"(r0), "=r"(r1), "=r"(r2), "=r"(r3) : "r"(a));
}
__device__ __forceinline__ unsigned packh2(float x, float y) {
    __half2 h = __floats2half2_rn(x, y);
    return *(unsigned*)&h;
}

// ---------------- fused pre-pass ----------------
// block ranges: [0,4096) src cvt, [4096,8192) tgt cvt,
// [8192,9216) W_src transcvt, [9216,9728) W_tgt, [9728,11264) W_out
__global__ void __launch_bounds__(256)
prepass(const float* __restrict__ src, __half* __restrict__ srch,
        const float* __restrict__ tgt, __half* __restrict__ tgth,
        const float* __restrict__ Wsrc, __half* __restrict__ wsrc_t,
        const float* __restrict__ Wtgt, __half* __restrict__ wtgt_t,
        const float* __restrict__ Wout, __half* __restrict__ wout_t)
{
    __shared__ __half tile[32][33];
    const int blk = blockIdx.x;
    const int tid = threadIdx.x;

    if (blk < 8192) {   // cvt jobs: 4096 blocks each, 256 thr x 1 float4
        const float4* in = (blk < 4096) ? (const float4*)src : (const float4*)tgt;
        __half2* out = (blk < 4096) ? (__half2*)srch : (__half2*)tgth;
        int i = (blk & 4095) * 256 + tid;
        float4 v = in[i];
        out[2*i]   = __floats2half2_rn(v.x, v.y);
        out[2*i+1] = __floats2half2_rn(v.z, v.w);
        return;
    }
    // transcvt jobs: in fp32 [K][N] -> out fp16 [N][K]
    const float* in; __half* out; int K, N, i;
    if (blk < 9216)      { in = Wsrc; out = wsrc_t; K = 512;  N = 2048; i = blk - 8192; }
    else if (blk < 9728) { in = Wtgt; out = wtgt_t; K = 512;  N = 1024; i = blk - 9216; }
    else                 { in = Wout; out = wout_t; K = 1536; N = 1024; i = blk - 9728; }
    int nb = N / 32;
    int n0 = (i % nb) * 32, k0 = (i / nb) * 32;
    int tx = tid & 31, ty = tid >> 5;
    #pragma unroll
    for (int j = 0; j < 4; ++j)
        tile[ty + 8*j][tx] = __float2half_rn(in[(size_t)(k0 + ty + 8*j) * N + n0 + tx]);
    __syncthreads();
    #pragma unroll
    for (int j = 0; j < 4; ++j)
        out[(size_t)(n0 + ty + 8*j) * K + k0 + tx] = tile[tx][ty + 8*j];
}

// ================= fp16 GEMM: C = relu(A @ Bt^T + bias) =================
#define BM 128
#define BN 128
#define BK 64
#define GLD 72
#define STAGE_H (2 * BM * GLD)
#define GEMM_SMEM (3 * STAGE_H * 2)

template<typename OutT, bool MERGED>
__global__ void __launch_bounds__(256, 2)
gemm_h(const __half* __restrict__ A0, int lda0, int kA0,
       const __half* __restrict__ A1, int lda1,
       const __half* __restrict__ Bt0, const float* __restrict__ bias0,
       OutT* __restrict__ C0, int ldc0,
       const __half* __restrict__ Bt1, const float* __restrict__ bias1,
       OutT* __restrict__ C1, int ldc1,
       int nx0, int K)
{
    extern __shared__ __half sm[];
    const int tid  = threadIdx.x;
    const int lane = tid & 31;
    const int warp = tid >> 5;
    const int wm   = warp & 3;
    const int wn   = warp >> 2;
    const int rowBase = blockIdx.y * BM;

    const bool sel0 = !MERGED || ((int)blockIdx.x < nx0);
    const int colBase = (sel0 ? blockIdx.x : blockIdx.x - nx0) * BN;
    const __half* Bt  = sel0 ? Bt0  : Bt1;
    const float* bias = sel0 ? bias0 : bias1;
    OutT* C           = sel0 ? C0   : C1;
    const int ldc     = sel0 ? ldc0 : ldc1;
    const __half* Am  = sel0 ? A0 : A1;
    const int ldam    = sel0 ? lda0 : lda1;

    const int T = K / BK;

    const int lmA_row = lane & 15;
    const int lmA_col = (lane >> 4) << 3;
    const int lmB_row = (lane & 7) + ((lane >> 4) << 3);
    const int lmB_col = lane & 8;

    auto stage = [&](int t) {
        __half* as = sm + (t % 3) * STAGE_H;
        __half* bs = as + BM * GLD;
        const int k0 = t * BK;
        const __half* Ap; int lda, kk;
        if (MERGED)            { Ap = Am; lda = ldam; kk = k0; }
        else if (k0 < kA0)     { Ap = A0; lda = lda0; kk = k0; }
        else                   { Ap = A1; lda = lda1; kk = k0 - kA0; }
        #pragma unroll
        for (int j = 0; j < 4; ++j) {
            int e = tid + j * 256;
            int row = e >> 3, sg = e & 7;
            cp_async16(as + row * GLD + sg * 8,
                       Ap + (size_t)(rowBase + row) * lda + kk + sg * 8);
        }
        #pragma unroll
        for (int j = 0; j < 4; ++j) {
            int e = tid + j * 256;
            int row = e >> 3, sg = e & 7;
            cp_async16(bs + row * GLD + sg * 8,
                       Bt + (size_t)(colBase + row) * K + k0 + sg * 8);
        }
        cp_commit();
    };

    float acc[2][8][4] = {};

    stage(0);
    stage(1);

    for (int t = 0; t < T; ++t) {
        if (t + 1 < T) cp_wait<1>(); else cp_wait<0>();
        __syncthreads();
        if (t + 2 < T) stage(t + 2);

        const __half* as = sm + (t % 3) * STAGE_H;
        const __half* bs = as + BM * GLD;
        #pragma unroll
        for (int kb = 0; kb < 4; ++kb) {
            const int kk = kb * 16;
            unsigned af[2][4], bf[8][2];
            #pragma unroll
            for (int mf = 0; mf < 2; ++mf)
                ldsm_x4(af[mf][0], af[mf][1], af[mf][2], af[mf][3],
                        as + (wm * 32 + mf * 16 + lmA_row) * GLD + kk + lmA_col);
            #pragma unroll
            for (int g = 0; g < 4; ++g)
                ldsm_x4(bf[2*g][0], bf[2*g][1], bf[2*g+1][0], bf[2*g+1][1],
                        bs + (wn * 64 + g * 16 + lmB_row) * GLD + kk + lmB_col);
            #pragma unroll
            for (int mf = 0; mf < 2; ++mf)
                #pragma unroll
                for (int nf = 0; nf < 8; ++nf)
                    mma_f16(acc[mf][nf], af[mf], bf[nf]);
        }
    }

    #pragma unroll
    for (int mf = 0; mf < 2; ++mf) {
        const int r0 = rowBase + wm * 32 + mf * 16 + (lane >> 2);
        #pragma unroll
        for (int nf = 0; nf < 8; ++nf) {
            const int c0 = colBase + wn * 64 + nf * 8 + (lane & 3) * 2;
            const float bz0 = bias[c0], bz1 = bias[c0 + 1];
            float v00 = fmaxf(acc[mf][nf][0] + bz0, 0.f);
            float v01 = fmaxf(acc[mf][nf][1] + bz1, 0.f);
            float v10 = fmaxf(acc[mf][nf][2] + bz0, 0.f);
            float v11 = fmaxf(acc[mf][nf][3] + bz1, 0.f);
            if constexpr (sizeof(OutT) == 2) {
                *(__half2*)((__half*)C + (size_t)r0 * ldc + c0) =
                    __floats2half2_rn(v00, v01);
                *(__half2*)((__half*)C + (size_t)(r0 + 8) * ldc + c0) =
                    __floats2half2_rn(v10, v11);
            } else {
                *(float2*)((float*)C + (size_t)r0 * ldc + c0)       = make_float2(v00, v01);
                *(float2*)((float*)C + (size_t)(r0 + 8) * ldc + c0) = make_float2(v10, v11);
            }
        }
    }
}

// ================= flash attention =================
// CTA = 128 q-rows x one (b,h). Online softmax; K/V double-buffered.
// smem: qs[128][QLD] + K bufs 2x[64][KLD] + V bufs 2x[64][KLD]
#define QLD 136
#define KLD 136
#define FA_SMEM ((128*QLD + 4*64*KLD) * 2)   // 104448 bytes

__global__ void __launch_bounds__(256, 2)
attn_flash(const __half* __restrict__ Q, const __half* __restrict__ KVg,
           __half* __restrict__ O)
{
    extern __shared__ __half sm[];
    __half* qs = sm;                               // [128][QLD]
    __half* kb0 = sm + 128 * QLD;                  // K buffers
    __half* vb0 = kb0 + 2 * 64 * KLD;              // V buffers

    const int tid  = threadIdx.x;
    const int lane = tid & 31;
    const int warp = tid >> 5;
    const int bh = blockIdx.y;
    const int b = bh >> 3, h = bh & 7;
    const int rt = blockIdx.x;                     // 0..3 (128 q-rows each)
    const float sc = 0.08838834764831845f;         // 1/sqrt(128)

    const __half* qg = Q   + ((size_t)(b * 512 + rt * 128)) * 1024 + h * 128;
    const __half* kg = KVg + ((size_t)(b * 512)) * 2048 + h * 128;
    const __half* vg = kg + 1024;
    __half*       og = O   + ((size_t)(b * 512 + rt * 128)) * 1024 + h * 128;

    const int lmA_row = lane & 15;
    const int lmA_col = (lane >> 4) << 3;
    const int lmB_row = (lane & 7) + ((lane >> 4) << 3);
    const int lmB_col = lane & 8;
    const int quad = lane >> 2, tq = lane & 3;

    auto issue_K = [&](int st) {
        __half* dst = kb0 + (st & 1) * 64 * KLD;
        #pragma unroll
        for (int j = 0; j < 4; ++j) {
            int e = tid + j * 256;
            int row = e >> 4, sg = e & 15;
            cp_async16(dst + row * KLD + sg * 8,
                       kg + (size_t)(st * 64 + row) * 2048 + sg * 8);
        }
        cp_commit();
    };
    auto issue_V = [&](int st) {
        __half* dst = vb0 + (st & 1) * 64 * KLD;
        #pragma unroll
        for (int j = 0; j < 4; ++j) {
            int e = tid + j * 256;
            int row = e >> 4, sg = e & 15;
            cp_async16(dst + row * KLD + sg * 8,
                       vg + (size_t)(st * 64 + row) * 2048 + sg * 8);
        }
        cp_commit();
    };

    // prologue: group0 = Q + K0, group1 = V0, group2 = K1
    {
        #pragma unroll
        for (int j = 0; j < 8; ++j) {
            int e = tid + j * 256;
            int row = e >> 4, sg = e & 15;
            cp_async16(qs + row * QLD + sg * 8,
                       qg + (size_t)row * 1024 + sg * 8);
        }
        issue_K(0);     // commits Q + K0
        issue_V(0);
        issue_K(1);
    }

    float oacc[16][4] = {};
    float m0 = -1e30f, m1 = -1e30f, l0 = 0.f, l1 = 0.f;

    for (int t = 0; t < 8; ++t) {
        // ---- wait K(t); S = Q @ K^T ----
        if (t < 7) cp_wait<2>(); else cp_wait<1>();
        __syncthreads();
        const __half* ks = kb0 + (t & 1) * 64 * KLD;
        float s[8][4] = {};
        #pragma unroll
        for (int kb = 0; kb < 8; ++kb) {
            unsigned a[4];
            ldsm_x4(a[0], a[1], a[2], a[3],
                    qs + (warp * 16 + lmA_row) * QLD + kb * 16 + lmA_col);
            #pragma unroll
            for (int g = 0; g < 4; ++g) {
                unsigned bf[2][2];
                ldsm_x4(bf[0][0], bf[0][1], bf[1][0], bf[1][1],
                        ks + (g * 16 + lmB_row) * KLD + kb * 16 + lmB_col);
                mma_f16(s[2*g],     a, bf[0]);
                mma_f16(s[2*g + 1], a, bf[1]);
            }
        }
        if (t + 1 < 8) issue_V(t + 1);   // other V buffer; safe

        // ---- online softmax ----
        float mn0 = m0, mn1 = m1;
        #pragma unroll
        for (int nf = 0; nf < 8; ++nf) {
            mn0 = fmaxf(mn0, fmaxf(s[nf][0], s[nf][1]));
            mn1 = fmaxf(mn1, fmaxf(s[nf][2], s[nf][3]));
        }
        mn0 = fmaxf(mn0, __shfl_xor_sync(0xffffffffu, mn0, 1));
        mn0 = fmaxf(mn0, __shfl_xor_sync(0xffffffffu, mn0, 2));
        mn1 = fmaxf(mn1, __shfl_xor_sync(0xffffffffu, mn1, 1));
        mn1 = fmaxf(mn1, __shfl_xor_sync(0xffffffffu, mn1, 2));
        const float a0 = __expf((m0 - mn0) * sc);
        const float a1 = __expf((m1 - mn1) * sc);
        m0 = mn0; m1 = mn1;

        unsigned pf[8][2];
        float ls0 = 0.f, ls1 = 0.f;
        #pragma unroll
        for (int nf = 0; nf < 8; ++nf) {
            float p0 = __expf((s[nf][0] - m0) * sc);
            float p1 = __expf((s[nf][1] - m0) * sc);
            float p2 = __expf((s[nf][2] - m1) * sc);
            float p3 = __expf((s[nf][3] - m1) * sc);
            ls0 += p0 + p1; ls1 += p2 + p3;
            pf[nf][0] = packh2(p0, p1);
            pf[nf][1] = packh2(p2, p3);
        }
        l0 = a0 * l0 + ls0;
        l1 = a1 * l1 + ls1;
        #pragma unroll
        for (int nf = 0; nf < 16; ++nf) {
            oacc[nf][0] *= a0; oacc[nf][1] *= a0;
            oacc[nf][2] *= a1; oacc[nf][3] *= a1;
        }

        // ---- wait V(t); O += P @ V ----
        if (t < 7) cp_wait<2>(); else cp_wait<0>();
        __syncthreads();
        const __half* vs = vb0 + (t & 1) * 64 * KLD;
        #pragma unroll
        for (int kb2 = 0; kb2 < 4; ++kb2) {
            unsigned pa[4] = { pf[2*kb2][0], pf[2*kb2][1],
                               pf[2*kb2 + 1][0], pf[2*kb2 + 1][1] };
            #pragma unroll
            for (int g = 0; g < 8; ++g) {
                unsigned bf[2][2];
                ldsm_x4_t(bf[0][0], bf[0][1], bf[1][0], bf[1][1],
                          vs + (kb2 * 16 + lmA_row) * KLD + g * 16 + lmA_col);
                mma_f16(oacc[2*g],     pa, bf[0]);
                mma_f16(oacc[2*g + 1], pa, bf[1]);
            }
        }
        if (t + 2 < 8) issue_K(t + 2);   // K buffer t&1; S(t) consumed by all warps
    }

    // ---- epilogue: normalize + store ----
    l0 += __shfl_xor_sync(0xffffffffu, l0, 1);
    l0 += __shfl_xor_sync(0xffffffffu, l0, 2);
    l1 += __shfl_xor_sync(0xffffffffu, l1, 1);
    l1 += __shfl_xor_sync(0xffffffffu, l1, 2);
    const float inv0 = 1.f / l0, inv1 = 1.f / l1;
    const int r0 = warp * 16 + quad;
    #pragma unroll
    for (int nf = 0; nf < 16; ++nf) {
        const int c0 = nf * 8 + tq * 2;
        *(__half2*)(og + (size_t)r0 * 1024 + c0) =
            __floats2half2_rn(oacc[nf][0] * inv0, oacc[nf][1] * inv0);
        *(__half2*)(og + (size_t)(r0 + 8) * 1024 + c0) =
            __floats2half2_rn(oacc[nf][2] * inv1, oacc[nf][3] * inv1);
    }
}

// ---------------- launch ----------------
extern "C" void kernel_launch(void* const* d_in, const int* in_sizes, int n_in,
                              void* d_out, int out_size)
{
    const float* src   = (const float*)d_in[0];
    const float* tgt   = (const float*)d_in[1];
    const float* W_src = (const float*)d_in[2];
    const float* b_src = (const float*)d_in[3];
    const float* W_tgt = (const float*)d_in[4];
    const float* b_tgt = (const float*)d_in[5];
    const float* W_out = (const float*)d_in[6];
    const float* b_out = (const float*)d_in[7];
    float* out = (float*)d_out;

    __half *srctran, *qh, *upd, *srch, *tgth, *wsrc_t, *wtgt_t, *wout_t;
    cudaGetSymbolAddress((void**)&srctran, g_srctran_h);
    cudaGetSymbolAddress((void**)&qh,      g_q_h);
    cudaGetSymbolAddress((void**)&upd,     g_upd_h);
    cudaGetSymbolAddress((void**)&srch,    g_src_h);
    cudaGetSymbolAddress((void**)&tgth,    g_tgt_h);
    cudaGetSymbolAddress((void**)&wsrc_t,  g_wsrc_t);
    cudaGetSymbolAddress((void**)&wtgt_t,  g_wtgt_t);
    cudaGetSymbolAddress((void**)&wout_t,  g_wout_t);

    cudaFuncSetAttribute((const void*)gemm_h<__half, true>,
                         cudaFuncAttributeMaxDynamicSharedMemorySize, GEMM_SMEM);
    cudaFuncSetAttribute((const void*)gemm_h<float, false>,
                         cudaFuncAttributeMaxDynamicSharedMemorySize, GEMM_SMEM);
    cudaFuncSetAttribute((const void*)attn_flash,
                         cudaFuncAttributeMaxDynamicSharedMemorySize, FA_SMEM);

    dim3 blk(256);

    // fused pre-pass (src/tgt cvt + 3 weight transposes)
    prepass<<<11264, blk>>>(src, srch, tgt, tgth,
                            W_src, wsrc_t, W_tgt, wtgt_t, W_out, wout_t);

    // GEMM1 + GEMM2 fused into one grid
    gemm_h<__half, true><<<dim3(16 + 8, 8192/BM), blk, GEMM_SMEM>>>(
        srch, 512, 512, tgth, 512,
        wsrc_t, b_src, srctran, 2048,
        wtgt_t, b_tgt, qh,      1024,
        16, 512);

    // flash attention
    attn_flash<<<dim3(4, 128), blk, FA_SMEM>>>(qh, srctran, upd);

    // GEMM3: out = relu([tgt | upd] @ W_out + b)  [8192,1536]x[1536,1024]
    gemm_h<float, false><<<dim3(1024/BN, 8192/BM), blk, GEMM_SMEM>>>(
        tgth, 512, 512, upd, 1024,
        wout_t, b_out, out, 1024,
        nullptr, nullptr, nullptr, 0,
        1024/BN, 1536);
}

// round 10
// speedup vs baseline: 18.2999x; 1.0210x over previous
#include <cuda_runtime.h>
#include <cuda_fp16.h>
#include <math.h>

// ---------------- scratch (static device globals; no allocation) ----------------
__device__ __half g_srctran_h[16*512*2048];  // relu(src@W_src+b), fp16 (K | V)
__device__ __half g_q_h     [16*512*1024];   // relu(tgt@W_tgt+b), fp16
__device__ __half g_upd_h   [16*512*1024];   // attention output, fp16
__device__ __half g_src_h   [16*512*512];
__device__ __half g_tgt_h   [16*512*512];
__device__ __half g_wsrc_h  [512*2048];      // W_src fp16, [K][N]
__device__ __half g_wtgt_h  [512*1024];      // W_tgt fp16, [K][N]
__device__ __half g_wout_h  [1536*1024];     // W_out fp16, [K][N]

// ---------------- PTX helpers ----------------
__device__ __forceinline__ void cp_async16(void* smem, const void* gmem) {
    unsigned s = (unsigned)__cvta_generic_to_shared(smem);
    asm volatile("cp.async.cg.shared.global [%0], [%1], 16;\n" :: "r"(s), "l"(gmem));
}
__device__ __forceinline__ void cp_commit() { asm volatile("cp.async.commit_group;\n"); }
template<int N> __device__ __forceinline__ void cp_wait() {
    asm volatile("cp.async.wait_group %0;\n" :: "n"(N));
}
__device__ __forceinline__ void mma_f16(float (&d)[4], const unsigned (&a)[4],
                                        const unsigned (&b)[2]) {
    asm volatile(
        "mma.sync.aligned.m16n8k16.row.col.f32.f16.f16.f32 "
        "{%0,%1,%2,%3}, {%4,%5,%6,%7}, {%8,%9}, {%0,%1,%2,%3};\n"
        : "+f"(d[0]), "+f"(d[1]), "+f"(d[2]), "+f"(d[3])
        : "r"(a[0]), "r"(a[1]), "r"(a[2]), "r"(a[3]), "r"(b[0]), "r"(b[1]));
}
__device__ __forceinline__ void ldsm_x4(unsigned &r0, unsigned &r1,
                                        unsigned &r2, unsigned &r3,
                                        const __half* p) {
    unsigned a = (unsigned)__cvta_generic_to_shared(p);
    asm volatile("ldmatrix.sync.aligned.m8n8.x4.shared.b16 {%0,%1,%2,%3}, [%4];\n"
                 : "=r"(r0), "=r"(r1), "=r"(r2), "=r"(r3) : "r"(a));
}
__device__ __forceinline__ void ldsm_x4_t(unsigned &r0, unsigned &r1,
                                          unsigned &r2, unsigned &r3,
                                          const __half* p) {
    unsigned a = (unsigned)__cvta_generic_to_shared(p);
    asm volatile("ldmatrix.sync.aligned.m8n8.x4.trans.shared.b16 {%0,%1,%2,%3}, [%4];\n"
                 : "=r"(r0), "=r"(r1), "=r"(r2), "=r"(r3) : "r"(a));
}
__device__ __forceinline__ unsigned packh2(float x, float y) {
    __half2 h = __floats2half2_rn(x, y);
    return *(unsigned*)&h;
}

// ---------------- fused pre-pass: five fp32->fp16 cvt jobs, one launch ----------
// block ranges (each block: 256 thr x 1 float4 = 1024 elems):
// [0,4096) src, [4096,8192) tgt, [8192,9216) W_src, [9216,9728) W_tgt,
// [9728,11264) W_out
__global__ void __launch_bounds__(256)
prepass(const float* __restrict__ src, __half* __restrict__ srch,
        const float* __restrict__ tgt, __half* __restrict__ tgth,
        const float* __restrict__ Wsrc, __half* __restrict__ wsrc_h,
        const float* __restrict__ Wtgt, __half* __restrict__ wtgt_h,
        const float* __restrict__ Wout, __half* __restrict__ wout_h)
{
    const int blk = blockIdx.x;
    const float4* in; __half2* out; int i;
    if (blk < 4096)      { in = (const float4*)src;  out = (__half2*)srch;   i = blk; }
    else if (blk < 8192) { in = (const float4*)tgt;  out = (__half2*)tgth;   i = blk - 4096; }
    else if (blk < 9216) { in = (const float4*)Wsrc; out = (__half2*)wsrc_h; i = blk - 8192; }
    else if (blk < 9728) { in = (const float4*)Wtgt; out = (__half2*)wtgt_h; i = blk - 9216; }
    else                 { in = (const float4*)Wout; out = (__half2*)wout_h; i = blk - 9728; }
    int e = i * 256 + threadIdx.x;
    float4 v = in[e];
    out[2*e]   = __floats2half2_rn(v.x, v.y);
    out[2*e+1] = __floats2half2_rn(v.z, v.w);
}

// ================= fp16 GEMM: C = relu(A @ B + bias) =================
// A fp16 [M][K]; B fp16 [K][N] (natural layout, ldsm.trans fragments).
// MERGED=true: two GEMMs share one grid (blockIdx.x < nx0 -> set0).
// MERGED=false: A is virtual concat (A0 first kA0 cols, then A1); set0 only.
#define BM 128
#define BN 128
#define BK 64
#define GLD 72                        // A tile leading dim (halfs)
#define BLD 136                       // B tile leading dim (halfs)
#define STAGE_H (BM * GLD + BK * BLD) // 17920 halfs per stage
#define GEMM_SMEM (3 * STAGE_H * 2)   // 107520 bytes

template<typename OutT, bool MERGED>
__global__ void __launch_bounds__(256, 2)
gemm_h(const __half* __restrict__ A0, int lda0, int kA0,
       const __half* __restrict__ A1, int lda1,
       const __half* __restrict__ Bw0, int ldb0, const float* __restrict__ bias0,
       OutT* __restrict__ C0, int ldc0,
       const __half* __restrict__ Bw1, int ldb1, const float* __restrict__ bias1,
       OutT* __restrict__ C1, int ldc1,
       int nx0, int K)
{
    extern __shared__ __half sm[];
    const int tid  = threadIdx.x;
    const int lane = tid & 31;
    const int warp = tid >> 5;
    const int wm   = warp & 3;    // 4 warps x 32 rows
    const int wn   = warp >> 2;   // 2 warps x 64 cols
    const int rowBase = blockIdx.y * BM;

    const bool sel0 = !MERGED || ((int)blockIdx.x < nx0);
    const int colBase = (sel0 ? blockIdx.x : blockIdx.x - nx0) * BN;
    const __half* Bw  = sel0 ? Bw0  : Bw1;
    const int ldb     = sel0 ? ldb0 : ldb1;
    const float* bias = sel0 ? bias0 : bias1;
    OutT* C           = sel0 ? C0   : C1;
    const int ldc     = sel0 ? ldc0 : ldc1;
    const __half* Am  = sel0 ? A0 : A1;
    const int ldam    = sel0 ? lda0 : lda1;

    const int T = K / BK;

    const int lmA_row = lane & 15;
    const int lmA_col = (lane >> 4) << 3;

    auto stage = [&](int t) {
        __half* as = sm + (t % 3) * STAGE_H;
        __half* bs = as + BM * GLD;
        const int k0 = t * BK;
        const __half* Ap; int lda, kk;
        if (MERGED)            { Ap = Am; lda = ldam; kk = k0; }
        else if (k0 < kA0)     { Ap = A0; lda = lda0; kk = k0; }
        else                   { Ap = A1; lda = lda1; kk = k0 - kA0; }
        // A tile: 128 rows x 64 halfs
        #pragma unroll
        for (int j = 0; j < 4; ++j) {
            int e = tid + j * 256;
            int row = e >> 3, sg = e & 7;
            cp_async16(as + row * GLD + sg * 8,
                       Ap + (size_t)(rowBase + row) * lda + kk + sg * 8);
        }
        // B tile: 64 k-rows x 128 n-halfs
        #pragma unroll
        for (int j = 0; j < 4; ++j) {
            int e = tid + j * 256;
            int row = e >> 4, sg = e & 15;
            cp_async16(bs + row * BLD + sg * 8,
                       Bw + (size_t)(k0 + row) * ldb + colBase + sg * 8);
        }
        cp_commit();
    };

    float acc[2][8][4] = {};

    stage(0);
    stage(1);

    for (int t = 0; t < T; ++t) {
        if (t + 1 < T) cp_wait<1>(); else cp_wait<0>();
        __syncthreads();
        if (t + 2 < T) stage(t + 2);

        const __half* as = sm + (t % 3) * STAGE_H;
        const __half* bs = as + BM * GLD;
        #pragma unroll
        for (int kb = 0; kb < 4; ++kb) {
            const int kk = kb * 16;
            unsigned af[2][4];
            #pragma unroll
            for (int mf = 0; mf < 2; ++mf)
                ldsm_x4(af[mf][0], af[mf][1], af[mf][2], af[mf][3],
                        as + (wm * 32 + mf * 16 + lmA_row) * GLD + kk + lmA_col);
            #pragma unroll
            for (int g = 0; g < 4; ++g) {
                unsigned bf[2][2];
                ldsm_x4_t(bf[0][0], bf[0][1], bf[1][0], bf[1][1],
                          bs + (kk + lmA_row) * BLD + wn * 64 + g * 16 + lmA_col);
                mma_f16(acc[0][2*g],     af[0], bf[0]);
                mma_f16(acc[0][2*g + 1], af[0], bf[1]);
                mma_f16(acc[1][2*g],     af[1], bf[0]);
                mma_f16(acc[1][2*g + 1], af[1], bf[1]);
            }
        }
    }

    #pragma unroll
    for (int mf = 0; mf < 2; ++mf) {
        const int r0 = rowBase + wm * 32 + mf * 16 + (lane >> 2);
        #pragma unroll
        for (int nf = 0; nf < 8; ++nf) {
            const int c0 = colBase + wn * 64 + nf * 8 + (lane & 3) * 2;
            const float bz0 = bias[c0], bz1 = bias[c0 + 1];
            float v00 = fmaxf(acc[mf][nf][0] + bz0, 0.f);
            float v01 = fmaxf(acc[mf][nf][1] + bz1, 0.f);
            float v10 = fmaxf(acc[mf][nf][2] + bz0, 0.f);
            float v11 = fmaxf(acc[mf][nf][3] + bz1, 0.f);
            if constexpr (sizeof(OutT) == 2) {
                *(__half2*)((__half*)C + (size_t)r0 * ldc + c0) =
                    __floats2half2_rn(v00, v01);
                *(__half2*)((__half*)C + (size_t)(r0 + 8) * ldc + c0) =
                    __floats2half2_rn(v10, v11);
            } else {
                *(float2*)((float*)C + (size_t)r0 * ldc + c0)       = make_float2(v00, v01);
                *(float2*)((float*)C + (size_t)(r0 + 8) * ldc + c0) = make_float2(v10, v11);
            }
        }
    }
}

// ================= flash attention (unchanged from R9) =================
#define QLD 136
#define KLD 136
#define FA_SMEM ((128*QLD + 4*64*KLD) * 2)   // 104448 bytes

__global__ void __launch_bounds__(256, 2)
attn_flash(const __half* __restrict__ Q, const __half* __restrict__ KVg,
           __half* __restrict__ O)
{
    extern __shared__ __half sm[];
    __half* qs = sm;                               // [128][QLD]
    __half* kb0 = sm + 128 * QLD;                  // K buffers
    __half* vb0 = kb0 + 2 * 64 * KLD;              // V buffers

    const int tid  = threadIdx.x;
    const int lane = tid & 31;
    const int warp = tid >> 5;
    const int bh = blockIdx.y;
    const int b = bh >> 3, h = bh & 7;
    const int rt = blockIdx.x;
    const float sc = 0.08838834764831845f;         // 1/sqrt(128)

    const __half* qg = Q   + ((size_t)(b * 512 + rt * 128)) * 1024 + h * 128;
    const __half* kg = KVg + ((size_t)(b * 512)) * 2048 + h * 128;
    const __half* vg = kg + 1024;
    __half*       og = O   + ((size_t)(b * 512 + rt * 128)) * 1024 + h * 128;

    const int lmA_row = lane & 15;
    const int lmA_col = (lane >> 4) << 3;
    const int lmB_row = (lane & 7) + ((lane >> 4) << 3);
    const int lmB_col = lane & 8;
    const int quad = lane >> 2, tq = lane & 3;

    auto issue_K = [&](int st) {
        __half* dst = kb0 + (st & 1) * 64 * KLD;
        #pragma unroll
        for (int j = 0; j < 4; ++j) {
            int e = tid + j * 256;
            int row = e >> 4, sg = e & 15;
            cp_async16(dst + row * KLD + sg * 8,
                       kg + (size_t)(st * 64 + row) * 2048 + sg * 8);
        }
        cp_commit();
    };
    auto issue_V = [&](int st) {
        __half* dst = vb0 + (st & 1) * 64 * KLD;
        #pragma unroll
        for (int j = 0; j < 4; ++j) {
            int e = tid + j * 256;
            int row = e >> 4, sg = e & 15;
            cp_async16(dst + row * KLD + sg * 8,
                       vg + (size_t)(st * 64 + row) * 2048 + sg * 8);
        }
        cp_commit();
    };

    {
        #pragma unroll
        for (int j = 0; j < 8; ++j) {
            int e = tid + j * 256;
            int row = e >> 4, sg = e & 15;
            cp_async16(qs + row * QLD + sg * 8,
                       qg + (size_t)row * 1024 + sg * 8);
        }
        issue_K(0);     // commits Q + K0
        issue_V(0);
        issue_K(1);
    }

    float oacc[16][4] = {};
    float m0 = -1e30f, m1 = -1e30f, l0 = 0.f, l1 = 0.f;

    for (int t = 0; t < 8; ++t) {
        if (t < 7) cp_wait<2>(); else cp_wait<1>();
        __syncthreads();
        const __half* ks = kb0 + (t & 1) * 64 * KLD;
        float s[8][4] = {};
        #pragma unroll
        for (int kb = 0; kb < 8; ++kb) {
            unsigned a[4];
            ldsm_x4(a[0], a[1], a[2], a[3],
                    qs + (warp * 16 + lmA_row) * QLD + kb * 16 + lmA_col);
            #pragma unroll
            for (int g = 0; g < 4; ++g) {
                unsigned bf[2][2];
                ldsm_x4(bf[0][0], bf[0][1], bf[1][0], bf[1][1],
                        ks + (g * 16 + lmB_row) * KLD + kb * 16 + lmB_col);
                mma_f16(s[2*g],     a, bf[0]);
                mma_f16(s[2*g + 1], a, bf[1]);
            }
        }
        if (t + 1 < 8) issue_V(t + 1);

        float mn0 = m0, mn1 = m1;
        #pragma unroll
        for (int nf = 0; nf < 8; ++nf) {
            mn0 = fmaxf(mn0, fmaxf(s[nf][0], s[nf][1]));
            mn1 = fmaxf(mn1, fmaxf(s[nf][2], s[nf][3]));
        }
        mn0 = fmaxf(mn0, __shfl_xor_sync(0xffffffffu, mn0, 1));
        mn0 = fmaxf(mn0, __shfl_xor_sync(0xffffffffu, mn0, 2));
        mn1 = fmaxf(mn1, __shfl_xor_sync(0xffffffffu, mn1, 1));
        mn1 = fmaxf(mn1, __shfl_xor_sync(0xffffffffu, mn1, 2));
        const float a0 = __expf((m0 - mn0) * sc);
        const float a1 = __expf((m1 - mn1) * sc);
        m0 = mn0; m1 = mn1;

        unsigned pf[8][2];
        float ls0 = 0.f, ls1 = 0.f;
        #pragma unroll
        for (int nf = 0; nf < 8; ++nf) {
            float p0 = __expf((s[nf][0] - m0) * sc);
            float p1 = __expf((s[nf][1] - m0) * sc);
            float p2 = __expf((s[nf][2] - m1) * sc);
            float p3 = __expf((s[nf][3] - m1) * sc);
            ls0 += p0 + p1; ls1 += p2 + p3;
            pf[nf][0] = packh2(p0, p1);
            pf[nf][1] = packh2(p2, p3);
        }
        l0 = a0 * l0 + ls0;
        l1 = a1 * l1 + ls1;
        #pragma unroll
        for (int nf = 0; nf < 16; ++nf) {
            oacc[nf][0] *= a0; oacc[nf][1] *= a0;
            oacc[nf][2] *= a1; oacc[nf][3] *= a1;
        }

        if (t < 7) cp_wait<2>(); else cp_wait<0>();
        __syncthreads();
        const __half* vs = vb0 + (t & 1) * 64 * KLD;
        #pragma unroll
        for (int kb2 = 0; kb2 < 4; ++kb2) {
            unsigned pa[4] = { pf[2*kb2][0], pf[2*kb2][1],
                               pf[2*kb2 + 1][0], pf[2*kb2 + 1][1] };
            #pragma unroll
            for (int g = 0; g < 8; ++g) {
                unsigned bf[2][2];
                ldsm_x4_t(bf[0][0], bf[0][1], bf[1][0], bf[1][1],
                          vs + (kb2 * 16 + lmA_row) * KLD + g * 16 + lmA_col);
                mma_f16(oacc[2*g],     pa, bf[0]);
                mma_f16(oacc[2*g + 1], pa, bf[1]);
            }
        }
        if (t + 2 < 8) issue_K(t + 2);
    }

    l0 += __shfl_xor_sync(0xffffffffu, l0, 1);
    l0 += __shfl_xor_sync(0xffffffffu, l0, 2);
    l1 += __shfl_xor_sync(0xffffffffu, l1, 1);
    l1 += __shfl_xor_sync(0xffffffffu, l1, 2);
    const float inv0 = 1.f / l0, inv1 = 1.f / l1;
    const int r0 = warp * 16 + quad;
    #pragma unroll
    for (int nf = 0; nf < 16; ++nf) {
        const int c0 = nf * 8 + tq * 2;
        *(__half2*)(og + (size_t)r0 * 1024 + c0) =
            __floats2half2_rn(oacc[nf][0] * inv0, oacc[nf][1] * inv0);
        *(__half2*)(og + (size_t)(r0 + 8) * 1024 + c0) =
            __floats2half2_rn(oacc[nf][2] * inv1, oacc[nf][3] * inv1);
    }
}

// ---------------- launch ----------------
extern "C" void kernel_launch(void* const* d_in, const int* in_sizes, int n_in,
                              void* d_out, int out_size)
{
    const float* src   = (const float*)d_in[0];
    const float* tgt   = (const float*)d_in[1];
    const float* W_src = (const float*)d_in[2];
    const float* b_src = (const float*)d_in[3];
    const float* W_tgt = (const float*)d_in[4];
    const float* b_tgt = (const float*)d_in[5];
    const float* W_out = (const float*)d_in[6];
    const float* b_out = (const float*)d_in[7];
    float* out = (float*)d_out;

    __half *srctran, *qh, *upd, *srch, *tgth, *wsrc_h, *wtgt_h, *wout_h;
    cudaGetSymbolAddress((void**)&srctran, g_srctran_h);
    cudaGetSymbolAddress((void**)&qh,      g_q_h);
    cudaGetSymbolAddress((void**)&upd,     g_upd_h);
    cudaGetSymbolAddress((void**)&srch,    g_src_h);
    cudaGetSymbolAddress((void**)&tgth,    g_tgt_h);
    cudaGetSymbolAddress((void**)&wsrc_h,  g_wsrc_h);
    cudaGetSymbolAddress((void**)&wtgt_h,  g_wtgt_h);
    cudaGetSymbolAddress((void**)&wout_h,  g_wout_h);

    cudaFuncSetAttribute((const void*)gemm_h<__half, true>,
                         cudaFuncAttributeMaxDynamicSharedMemorySize, GEMM_SMEM);
    cudaFuncSetAttribute((const void*)gemm_h<float, false>,
                         cudaFuncAttributeMaxDynamicSharedMemorySize, GEMM_SMEM);
    cudaFuncSetAttribute((const void*)attn_flash,
                         cudaFuncAttributeMaxDynamicSharedMemorySize, FA_SMEM);

    dim3 blk(256);

    // fused pre-pass: all five fp32->fp16 conversions, one launch
    prepass<<<11264, blk>>>(src, srch, tgt, tgth,
                            W_src, wsrc_h, W_tgt, wtgt_h, W_out, wout_h);

    // GEMM1 + GEMM2 fused into one grid
    gemm_h<__half, true><<<dim3(16 + 8, 8192/BM), blk, GEMM_SMEM>>>(
        srch, 512, 512, tgth, 512,
        wsrc_h, 2048, b_src, srctran, 2048,
        wtgt_h, 1024, b_tgt, qh,      1024,
        16, 512);

    // flash attention
    attn_flash<<<dim3(4, 128), blk, FA_SMEM>>>(qh, srctran, upd);

    // GEMM3: out = relu([tgt | upd] @ W_out + b)  [8192,1536]x[1536,1024]
    gemm_h<float, false><<<dim3(1024/BN, 8192/BM), blk, GEMM_SMEM>>>(
        tgth, 512, 512, upd, 1024,
        wout_h, 1024, b_out, out, 1024,
        nullptr, 0, nullptr, nullptr, 0,
        1024/BN, 1536);
}